// round 10
// baseline (speedup 1.0000x reference)
#include <cuda_runtime.h>
#include <cuda_fp16.h>
#include <stdint.h>
#include <math.h>

#define NN 50000
#define EE 800000
#define ETOT 850000
#define NEG 0.2f

// ---------------- scratch (static device globals) -------------------------
__device__ int    g_cnt[NN];
__device__ int    g_cur[NN];
__device__ int    g_rowptr[NN + 1];
__device__ int    g_col[ETOT];
__device__ __half g_h16[(size_t)NN * 160];
__device__ float  g_x1[(size_t)NN * 128];
__device__ float  g_x2[(size_t)NN * 128];
__device__ __align__(16) float4 g_as[NN];
__device__ __align__(16) float4 g_ad[NN];

// ---------------- CSR build ----------------------------------------------
__global__ void k_hist(const int* __restrict__ ei) {
    int e = blockIdx.x * blockDim.x + threadIdx.x;
    if (e >= ETOT) return;
    int d = (e < EE) ? ei[EE + e] : (e - EE);
    atomicAdd(&g_cnt[d], 1);
}

__global__ void k_scan() {
    const int CH = (NN + 1023) / 1024;  // 49
    __shared__ int warp_sums[32];
    int tid = threadIdx.x;
    int lane = tid & 31, wid = tid >> 5;
    int base = tid * CH;
    int local = 0;
    for (int i = 0; i < CH; i++) {
        int idx = base + i;
        if (idx < NN) local += g_cnt[idx];
    }
    int x = local;
    #pragma unroll
    for (int off = 1; off < 32; off <<= 1) {
        int y = __shfl_up_sync(0xffffffffu, x, off);
        if (lane >= off) x += y;
    }
    if (lane == 31) warp_sums[wid] = x;
    __syncthreads();
    if (wid == 0) {
        int w = warp_sums[lane];
        #pragma unroll
        for (int off = 1; off < 32; off <<= 1) {
            int y = __shfl_up_sync(0xffffffffu, w, off);
            if (lane >= off) w += y;
        }
        warp_sums[lane] = w;
    }
    __syncthreads();
    int ex = x - local + ((wid == 0) ? 0 : warp_sums[wid - 1]);
    int running = ex;
    for (int i = 0; i < CH; i++) {
        int idx = base + i;
        if (idx < NN) { g_rowptr[idx] = running; running += g_cnt[idx]; }
    }
    if (tid == 1023) g_rowptr[NN] = running;
}

__global__ void k_scatter(const int* __restrict__ ei) {
    int e = blockIdx.x * blockDim.x + threadIdx.x;
    if (e >= ETOT) return;
    int s, d;
    if (e < EE) { s = ei[e]; d = ei[EE + e]; }
    else        { s = d = e - EE; }
    int pos = g_rowptr[d] + atomicAdd(&g_cur[d], 1);
    g_col[pos] = s;
}

// ---------------- tf32x2 tensor-core GEMM (fp16 output) -------------------
__device__ __forceinline__ uint32_t f2tf32(float x) {
    uint32_t r;
    asm("cvt.rna.tf32.f32 %0, %1;" : "=r"(r) : "f"(x));
    return r;
}

__device__ __forceinline__ void split4(float4 v, float4& h4, float4& l4) {
    h4.x = __uint_as_float(f2tf32(v.x)); l4.x = __uint_as_float(f2tf32(v.x - h4.x));
    h4.y = __uint_as_float(f2tf32(v.y)); l4.y = __uint_as_float(f2tf32(v.y - h4.y));
    h4.z = __uint_as_float(f2tf32(v.z)); l4.z = __uint_as_float(f2tf32(v.z - h4.z));
    h4.w = __uint_as_float(f2tf32(v.w)); l4.w = __uint_as_float(f2tf32(v.w - h4.w));
}

__device__ __forceinline__ void mma_tf32(float* d, const uint32_t* a, const uint32_t* b) {
    asm volatile(
        "mma.sync.aligned.m16n8k8.row.col.f32.tf32.tf32.f32 "
        "{%0,%1,%2,%3}, {%4,%5,%6,%7}, {%8,%9}, {%0,%1,%2,%3};\n"
        : "+f"(d[0]), "+f"(d[1]), "+f"(d[2]), "+f"(d[3])
        : "r"(a[0]), "r"(a[1]), "r"(a[2]), "r"(a[3]), "r"(b[0]), "r"(b[1]));
}

// C16[M,BN] = half(A[M,128] @ B[128,BN]).  64xBN block tile, warp = 32x32.
// warp grid: 2 (m) x BN/32 (n).  FUSE (BN=128): attention coeffs to g_as/g_ad.
template<int BN, bool FUSE>
__global__ void __launch_bounds__(64 * (BN / 32))
k_tgemm(const float* __restrict__ A, const float* __restrict__ B,
        __half* __restrict__ C16,
        const float* __restrict__ a_s, const float* __restrict__ a_d) {
    const int NWN = BN / 32;
    const int NT = 64 * NWN;
    const int PA = 20;        // 20 mod 32 -> conflict-free frag loads
    const int PB = BN + 8;    // (BN+8) mod 32 == 8 -> conflict-free
    __shared__ float As[2][64 * PA];
    __shared__ float Bs[2][16 * (BN + 8)];
    const int tid = threadIdx.x;
    const int w = tid >> 5, lane = tid & 31;
    const int wm = w / NWN, wn = w % NWN;
    const int row0 = blockIdx.x * 64;
    const int g = lane >> 2, t4 = lane & 3;

    float acc[2][4][4];
    #pragma unroll
    for (int mt = 0; mt < 2; mt++)
        #pragma unroll
        for (int nt = 0; nt < 4; nt++)
            #pragma unroll
            for (int i = 0; i < 4; i++) acc[mt][nt][i] = 0.f;

    for (int kk = 0; kk < 128; kk += 16) {
        // A tile: 64 rows x 16 cols (float4 granularity), split hi/lo
        for (int idx = tid; idx < 256; idx += NT) {
            int r = idx >> 2, c4 = idx & 3;
            int gr = row0 + r;
            float4 v = make_float4(0.f, 0.f, 0.f, 0.f);
            if (gr < NN) v = *(const float4*)(A + (size_t)gr * 128 + kk + c4 * 4);
            float4 h4, l4;
            split4(v, h4, l4);
            *(float4*)&As[0][r * PA + c4 * 4] = h4;
            *(float4*)&As[1][r * PA + c4 * 4] = l4;
        }
        // B tile: 16 x BN
        for (int idx = tid; idx < 4 * BN; idx += NT) {
            int r = idx / (BN / 4), c = idx % (BN / 4);
            float4 v = *(const float4*)(B + (size_t)(kk + r) * BN + c * 4);
            float4 h4, l4;
            split4(v, h4, l4);
            *(float4*)&Bs[0][r * PB + c * 4] = h4;
            *(float4*)&Bs[1][r * PB + c * 4] = l4;
        }
        __syncthreads();
        #pragma unroll
        for (int s0 = 0; s0 < 2; s0++) {
            const int ko = s0 * 8;
            uint32_t bh[4][2], bl[4][2];
            #pragma unroll
            for (int nt = 0; nt < 4; nt++) {
                int colb = wn * 32 + nt * 8 + g;
                bh[nt][0] = __float_as_uint(Bs[0][(ko + t4) * PB + colb]);
                bh[nt][1] = __float_as_uint(Bs[0][(ko + 4 + t4) * PB + colb]);
                bl[nt][0] = __float_as_uint(Bs[1][(ko + t4) * PB + colb]);
                bl[nt][1] = __float_as_uint(Bs[1][(ko + 4 + t4) * PB + colb]);
            }
            #pragma unroll
            for (int mt = 0; mt < 2; mt++) {
                const int rb = wm * 32 + mt * 16;
                uint32_t ah[4], al[4];
                ah[0] = __float_as_uint(As[0][(rb + g) * PA + ko + t4]);
                ah[1] = __float_as_uint(As[0][(rb + 8 + g) * PA + ko + t4]);
                ah[2] = __float_as_uint(As[0][(rb + g) * PA + ko + 4 + t4]);
                ah[3] = __float_as_uint(As[0][(rb + 8 + g) * PA + ko + 4 + t4]);
                al[0] = __float_as_uint(As[1][(rb + g) * PA + ko + t4]);
                al[1] = __float_as_uint(As[1][(rb + 8 + g) * PA + ko + t4]);
                al[2] = __float_as_uint(As[1][(rb + g) * PA + ko + 4 + t4]);
                al[3] = __float_as_uint(As[1][(rb + 8 + g) * PA + ko + 4 + t4]);
                #pragma unroll
                for (int nt = 0; nt < 4; nt++) {
                    mma_tf32(acc[mt][nt], ah, bh[nt]);
                    mma_tf32(acc[mt][nt], ah, bl[nt]);
                    mma_tf32(acc[mt][nt], al, bh[nt]);
                }
            }
        }
        __syncthreads();
    }
    // store C as fp16
    #pragma unroll
    for (int mt = 0; mt < 2; mt++) {
        int r0 = row0 + wm * 32 + mt * 16 + g;
        #pragma unroll
        for (int nt = 0; nt < 4; nt++) {
            int cc = wn * 32 + nt * 8 + 2 * t4;
            if (r0 < NN)
                *(__half2*)(C16 + (size_t)r0 * BN + cc) =
                    __floats2half2_rn(acc[mt][nt][0], acc[mt][nt][1]);
            if (r0 + 8 < NN)
                *(__half2*)(C16 + (size_t)(r0 + 8) * BN + cc) =
                    __floats2half2_rn(acc[mt][nt][2], acc[mt][nt][3]);
        }
    }
    if (FUSE) {
        // head == wn (warp owns a full 32-col head slab); reduce over 4 t4 lanes
        float asv[4][2], adv[4][2];
        #pragma unroll
        for (int nt = 0; nt < 4; nt++) {
            int c = wn * 32 + nt * 8 + 2 * t4;
            asv[nt][0] = a_s[c]; asv[nt][1] = a_s[c + 1];
            adv[nt][0] = a_d[c]; adv[nt][1] = a_d[c + 1];
        }
        float* gasf = (float*)g_as;
        float* gadf = (float*)g_ad;
        #pragma unroll
        for (int mt = 0; mt < 2; mt++) {
            #pragma unroll
            for (int hf = 0; hf < 2; hf++) {
                int r = row0 + wm * 32 + mt * 16 + hf * 8 + g;
                float pa = 0.f, pd = 0.f;
                #pragma unroll
                for (int nt = 0; nt < 4; nt++) {
                    pa = fmaf(acc[mt][nt][2 * hf], asv[nt][0], pa);
                    pa = fmaf(acc[mt][nt][2 * hf + 1], asv[nt][1], pa);
                    pd = fmaf(acc[mt][nt][2 * hf], adv[nt][0], pd);
                    pd = fmaf(acc[mt][nt][2 * hf + 1], adv[nt][1], pd);
                }
                pa += __shfl_xor_sync(0xffffffffu, pa, 1);
                pa += __shfl_xor_sync(0xffffffffu, pa, 2);
                pd += __shfl_xor_sync(0xffffffffu, pd, 1);
                pd += __shfl_xor_sync(0xffffffffu, pd, 2);
                if (t4 == 0 && r < NN) {
                    gasf[r * 4 + wn] = pa;
                    gadf[r * 4 + wn] = pd;
                }
            }
        }
    }
}

// ---------------- per-node attention coefficients (layer 3, C=40) --------
__global__ void k_alpha40(const __half* __restrict__ h, const float* __restrict__ a_s,
                          const float* __restrict__ a_d) {
    int warp = (blockIdx.x * blockDim.x + threadIdx.x) >> 5;
    if (warp >= NN) return;
    int lane = threadIdx.x & 31;
    float pa[4], pd[4];
    #pragma unroll
    for (int hh = 0; hh < 4; hh++) {
        float hv = __half2float(h[(size_t)warp * 160 + hh * 40 + lane]);
        pa[hh] = hv * a_s[hh * 40 + lane];
        pd[hh] = hv * a_d[hh * 40 + lane];
        if (lane < 8) {
            float hv2 = __half2float(h[(size_t)warp * 160 + hh * 40 + 32 + lane]);
            pa[hh] = fmaf(hv2, a_s[hh * 40 + 32 + lane], pa[hh]);
            pd[hh] = fmaf(hv2, a_d[hh * 40 + 32 + lane], pd[hh]);
        }
    }
    #pragma unroll
    for (int hh = 0; hh < 4; hh++) {
        #pragma unroll
        for (int off = 16; off; off >>= 1) {
            pa[hh] += __shfl_xor_sync(0xffffffffu, pa[hh], off);
            pd[hh] += __shfl_xor_sync(0xffffffffu, pd[hh], off);
        }
    }
    if (lane == 0) {
        g_as[warp] = make_float4(pa[0], pa[1], pa[2], pa[3]);
        g_ad[warp] = make_float4(pd[0], pd[1], pd[2], pd[3]);
    }
}

// ---------------- aggregation, concat layers (128 ch, fp16 gather) -------
__global__ void k_agg128(const __half* __restrict__ h, const float* __restrict__ bias,
                         const float* __restrict__ resid, float* __restrict__ out) {
    int warp = (blockIdx.x * blockDim.x + threadIdx.x) >> 5;
    if (warp >= NN) return;
    int lane = threadIdx.x & 31;
    int hd = lane >> 3;
    float adv = ((const float*)&g_ad[warp])[hd];
    int beg = g_rowptr[warp], end = g_rowptr[warp + 1];
    const float* gasf = (const float*)g_as;

    float4 acc = make_float4(0.f, 0.f, 0.f, 0.f);
    float ss = 0.f;
    #pragma unroll 4
    for (int j = beg; j < end; j++) {
        int s = __ldg(&g_col[j]);
        float e = gasf[s * 4 + hd] + adv;
        e = e > 0.f ? e : NEG * e;
        float w = __expf(e);
        ss += w;
        uint2 hraw = *(const uint2*)(h + (size_t)s * 128 + lane * 4);
        float2 f0 = __half22float2(*(__half2*)&hraw.x);
        float2 f1 = __half22float2(*(__half2*)&hraw.y);
        acc.x = fmaf(w, f0.x, acc.x);
        acc.y = fmaf(w, f0.y, acc.y);
        acc.z = fmaf(w, f1.x, acc.z);
        acc.w = fmaf(w, f1.y, acc.w);
    }
    float inv = 1.f / ss;
    int ch = lane * 4;
    float4 b = *(const float4*)(bias + ch);
    float4 o = make_float4(acc.x * inv + b.x, acc.y * inv + b.y,
                           acc.z * inv + b.z, acc.w * inv + b.w);
    if (resid) {
        float4 r = *(const float4*)(resid + (size_t)warp * 128 + ch);
        o.x += r.x; o.y += r.y; o.z += r.z; o.w += r.w;
    }
    o.x = o.x > 0.f ? o.x : (__expf(o.x) - 1.f);
    o.y = o.y > 0.f ? o.y : (__expf(o.y) - 1.f);
    o.z = o.z > 0.f ? o.z : (__expf(o.z) - 1.f);
    o.w = o.w > 0.f ? o.w : (__expf(o.w) - 1.f);
    *(float4*)(out + (size_t)warp * 128 + ch) = o;
}

// ---------------- aggregation, final layer (160 -> head-mean 40) ---------
__global__ void k_agg40(const __half* __restrict__ h, const float* __restrict__ b3,
                        float* __restrict__ out) {
    int warp = (blockIdx.x * blockDim.x + threadIdx.x) >> 5;
    if (warp >= NN) return;
    int lane = threadIdx.x & 31;
    int hd = lane >> 3;
    float adv = ((const float*)&g_ad[warp])[hd];
    int beg = g_rowptr[warp], end = g_rowptr[warp + 1];
    const float* gasf = (const float*)g_as;

    float acc[5] = {0.f, 0.f, 0.f, 0.f, 0.f};
    float ss = 0.f;
    #pragma unroll 2
    for (int j = beg; j < end; j++) {
        int s = __ldg(&g_col[j]);
        float e = gasf[s * 4 + hd] + adv;
        e = e > 0.f ? e : NEG * e;
        float w = __expf(e);
        ss += w;
        const __half* hp = h + (size_t)s * 160 + lane * 5;
        #pragma unroll
        for (int i = 0; i < 5; i++)
            acc[i] = fmaf(w, __half2float(__ldg(hp + i)), acc[i]);
    }
    float inv = 1.f / ss;
    float r[5];
    #pragma unroll
    for (int i = 0; i < 5; i++) {
        float v = acc[i] * inv;
        v += __shfl_xor_sync(0xffffffffu, v, 8);
        v += __shfl_xor_sync(0xffffffffu, v, 16);
        r[i] = v * 0.25f;
    }
    if (lane < 8) {
        int c0 = lane * 5;
        #pragma unroll
        for (int i = 0; i < 5; i++)
            out[(size_t)warp * 40 + c0 + i] = r[i] + b3[c0 + i];
    }
}

// ---------------- launch ---------------------------------------------------
extern "C" void kernel_launch(void* const* d_in, const int* in_sizes, int n_in,
                              void* d_out, int out_size) {
    const float* x   = (const float*)d_in[0];
    const int*   ei  = (const int*)d_in[1];
    const float* W1  = (const float*)d_in[2];
    const float* as1 = (const float*)d_in[3];
    const float* ad1 = (const float*)d_in[4];
    const float* b1  = (const float*)d_in[5];
    const float* W2  = (const float*)d_in[6];
    const float* as2 = (const float*)d_in[7];
    const float* ad2 = (const float*)d_in[8];
    const float* b2  = (const float*)d_in[9];
    const float* W3  = (const float*)d_in[10];
    const float* as3 = (const float*)d_in[11];
    const float* ad3 = (const float*)d_in[12];
    const float* b3  = (const float*)d_in[13];
    float* out = (float*)d_out;

    __half* g_h_p;
    float *g_x1_p, *g_x2_p;
    void *cnt_p, *cur_p;
    cudaGetSymbolAddress((void**)&g_h_p,  g_h16);
    cudaGetSymbolAddress((void**)&g_x1_p, g_x1);
    cudaGetSymbolAddress((void**)&g_x2_p, g_x2);
    cudaGetSymbolAddress(&cnt_p, g_cnt);
    cudaGetSymbolAddress(&cur_p, g_cur);

    const int WB = 256;
    const int nodeBlocks = (NN * 32 + WB - 1) / WB;
    const int edgeBlocks = (ETOT + 255) / 256;
    const int gemmBlocks = (NN + 63) / 64;

    // Fork a side stream for the CSR build; it runs concurrently with the
    // layer-1 GEMM (fully independent) and joins before the first aggregation.
    // Stream/event create+destroy is host-side only (capture-time), legal.
    cudaStream_t s1;
    cudaStreamCreateWithFlags(&s1, cudaStreamNonBlocking);
    cudaEvent_t evFork, evCsr;
    cudaEventCreateWithFlags(&evFork, cudaEventDisableTiming);
    cudaEventCreateWithFlags(&evCsr,  cudaEventDisableTiming);

    cudaEventRecord(evFork, 0);
    cudaStreamWaitEvent(s1, evFork, 0);

    // ---- CSR build on side stream ----
    cudaMemsetAsync(cnt_p, 0, NN * sizeof(int), s1);
    cudaMemsetAsync(cur_p, 0, NN * sizeof(int), s1);
    k_hist<<<edgeBlocks, 256, 0, s1>>>(ei);
    k_scan<<<1, 1024, 0, s1>>>();
    k_scatter<<<edgeBlocks, 256, 0, s1>>>(ei);
    cudaEventRecord(evCsr, s1);

    // ---- layer 1 (GEMM overlaps CSR build) ----
    k_tgemm<128, true><<<gemmBlocks, 256>>>(x, W1, g_h_p, as1, ad1);
    cudaStreamWaitEvent(0, evCsr, 0);   // join: agg needs rowptr/col
    k_agg128<<<nodeBlocks, WB>>>(g_h_p, b1, nullptr, g_x1_p);

    // ---- layer 2 ----
    k_tgemm<128, true><<<gemmBlocks, 256>>>(g_x1_p, W2, g_h_p, as2, ad2);
    k_agg128<<<nodeBlocks, WB>>>(g_h_p, b2, g_x1_p, g_x2_p);

    // ---- layer 3 ----
    k_tgemm<160, false><<<gemmBlocks, 320>>>(g_x2_p, W3, g_h_p, nullptr, nullptr);
    k_alpha40<<<nodeBlocks, WB>>>(g_h_p, as3, ad3);
    k_agg40<<<nodeBlocks, WB>>>(g_h_p, b3, out);

    cudaEventDestroy(evFork);
    cudaEventDestroy(evCsr);
    cudaStreamDestroy(s1);
}

// round 11
// speedup vs baseline: 1.0224x; 1.0224x over previous
#include <cuda_runtime.h>
#include <cuda_fp16.h>
#include <stdint.h>
#include <math.h>

#define NN 50000
#define EE 800000
#define ETOT 850000
#define NEG 0.2f

// ---------------- scratch (static device globals) -------------------------
__device__ int    g_cnt[NN];
__device__ int    g_cur[NN];
__device__ int    g_rowptr[NN + 1];
__device__ int    g_col[ETOT];
__device__ __half g_h16[(size_t)NN * 160];
__device__ float  g_x1[(size_t)NN * 128];
__device__ float  g_x2[(size_t)NN * 128];
__device__ __align__(16) float4 g_as[NN];
__device__ __align__(16) float4 g_ad[NN];

// ---------------- CSR build ----------------------------------------------
__global__ void k_hist(const int* __restrict__ ei) {
    int e = blockIdx.x * blockDim.x + threadIdx.x;
    if (e >= ETOT) return;
    int d = (e < EE) ? ei[EE + e] : (e - EE);
    atomicAdd(&g_cnt[d], 1);
}

__global__ void k_scan() {
    const int CH = (NN + 1023) / 1024;  // 49
    __shared__ int warp_sums[32];
    int tid = threadIdx.x;
    int lane = tid & 31, wid = tid >> 5;
    int base = tid * CH;
    int local = 0;
    for (int i = 0; i < CH; i++) {
        int idx = base + i;
        if (idx < NN) local += g_cnt[idx];
    }
    int x = local;
    #pragma unroll
    for (int off = 1; off < 32; off <<= 1) {
        int y = __shfl_up_sync(0xffffffffu, x, off);
        if (lane >= off) x += y;
    }
    if (lane == 31) warp_sums[wid] = x;
    __syncthreads();
    if (wid == 0) {
        int w = warp_sums[lane];
        #pragma unroll
        for (int off = 1; off < 32; off <<= 1) {
            int y = __shfl_up_sync(0xffffffffu, w, off);
            if (lane >= off) w += y;
        }
        warp_sums[lane] = w;
    }
    __syncthreads();
    int ex = x - local + ((wid == 0) ? 0 : warp_sums[wid - 1]);
    int running = ex;
    for (int i = 0; i < CH; i++) {
        int idx = base + i;
        if (idx < NN) { g_rowptr[idx] = running; running += g_cnt[idx]; }
    }
    if (tid == 1023) g_rowptr[NN] = running;
}

__global__ void k_scatter(const int* __restrict__ ei) {
    int e = blockIdx.x * blockDim.x + threadIdx.x;
    if (e >= ETOT) return;
    int s, d;
    if (e < EE) { s = ei[e]; d = ei[EE + e]; }
    else        { s = d = e - EE; }
    int pos = g_rowptr[d] + atomicAdd(&g_cur[d], 1);
    g_col[pos] = s;
}

// ---------------- tf32x2 tensor-core GEMM (fp16 output) -------------------
__device__ __forceinline__ uint32_t f2tf32(float x) {
    uint32_t r;
    asm("cvt.rna.tf32.f32 %0, %1;" : "=r"(r) : "f"(x));
    return r;
}

__device__ __forceinline__ void split4(float4 v, float4& h4, float4& l4) {
    h4.x = __uint_as_float(f2tf32(v.x)); l4.x = __uint_as_float(f2tf32(v.x - h4.x));
    h4.y = __uint_as_float(f2tf32(v.y)); l4.y = __uint_as_float(f2tf32(v.y - h4.y));
    h4.z = __uint_as_float(f2tf32(v.z)); l4.z = __uint_as_float(f2tf32(v.z - h4.z));
    h4.w = __uint_as_float(f2tf32(v.w)); l4.w = __uint_as_float(f2tf32(v.w - h4.w));
}

__device__ __forceinline__ void mma_tf32(float* d, const uint32_t* a, const uint32_t* b) {
    asm volatile(
        "mma.sync.aligned.m16n8k8.row.col.f32.tf32.tf32.f32 "
        "{%0,%1,%2,%3}, {%4,%5,%6,%7}, {%8,%9}, {%0,%1,%2,%3};\n"
        : "+f"(d[0]), "+f"(d[1]), "+f"(d[2]), "+f"(d[3])
        : "r"(a[0]), "r"(a[1]), "r"(a[2]), "r"(a[3]), "r"(b[0]), "r"(b[1]));
}

// C16[M,BN] = half(A[M,128] @ B[128,BN]).  64xBN block tile, warp = 32x32.
template<int BN, bool FUSE>
__global__ void __launch_bounds__(64 * (BN / 32))
k_tgemm(const float* __restrict__ A, const float* __restrict__ B,
        __half* __restrict__ C16,
        const float* __restrict__ a_s, const float* __restrict__ a_d) {
    const int NWN = BN / 32;
    const int NT = 64 * NWN;
    const int PA = 20;
    const int PB = BN + 8;
    __shared__ float As[2][64 * PA];
    __shared__ float Bs[2][16 * (BN + 8)];
    const int tid = threadIdx.x;
    const int w = tid >> 5, lane = tid & 31;
    const int wm = w / NWN, wn = w % NWN;
    const int row0 = blockIdx.x * 64;
    const int g = lane >> 2, t4 = lane & 3;

    float acc[2][4][4];
    #pragma unroll
    for (int mt = 0; mt < 2; mt++)
        #pragma unroll
        for (int nt = 0; nt < 4; nt++)
            #pragma unroll
            for (int i = 0; i < 4; i++) acc[mt][nt][i] = 0.f;

    for (int kk = 0; kk < 128; kk += 16) {
        for (int idx = tid; idx < 256; idx += NT) {
            int r = idx >> 2, c4 = idx & 3;
            int gr = row0 + r;
            float4 v = make_float4(0.f, 0.f, 0.f, 0.f);
            if (gr < NN) v = *(const float4*)(A + (size_t)gr * 128 + kk + c4 * 4);
            float4 h4, l4;
            split4(v, h4, l4);
            *(float4*)&As[0][r * PA + c4 * 4] = h4;
            *(float4*)&As[1][r * PA + c4 * 4] = l4;
        }
        for (int idx = tid; idx < 4 * BN; idx += NT) {
            int r = idx / (BN / 4), c = idx % (BN / 4);
            float4 v = *(const float4*)(B + (size_t)(kk + r) * BN + c * 4);
            float4 h4, l4;
            split4(v, h4, l4);
            *(float4*)&Bs[0][r * PB + c * 4] = h4;
            *(float4*)&Bs[1][r * PB + c * 4] = l4;
        }
        __syncthreads();
        #pragma unroll
        for (int s0 = 0; s0 < 2; s0++) {
            const int ko = s0 * 8;
            uint32_t bh[4][2], bl[4][2];
            #pragma unroll
            for (int nt = 0; nt < 4; nt++) {
                int colb = wn * 32 + nt * 8 + g;
                bh[nt][0] = __float_as_uint(Bs[0][(ko + t4) * PB + colb]);
                bh[nt][1] = __float_as_uint(Bs[0][(ko + 4 + t4) * PB + colb]);
                bl[nt][0] = __float_as_uint(Bs[1][(ko + t4) * PB + colb]);
                bl[nt][1] = __float_as_uint(Bs[1][(ko + 4 + t4) * PB + colb]);
            }
            #pragma unroll
            for (int mt = 0; mt < 2; mt++) {
                const int rb = wm * 32 + mt * 16;
                uint32_t ah[4], al[4];
                ah[0] = __float_as_uint(As[0][(rb + g) * PA + ko + t4]);
                ah[1] = __float_as_uint(As[0][(rb + 8 + g) * PA + ko + t4]);
                ah[2] = __float_as_uint(As[0][(rb + g) * PA + ko + 4 + t4]);
                ah[3] = __float_as_uint(As[0][(rb + 8 + g) * PA + ko + 4 + t4]);
                al[0] = __float_as_uint(As[1][(rb + g) * PA + ko + t4]);
                al[1] = __float_as_uint(As[1][(rb + 8 + g) * PA + ko + t4]);
                al[2] = __float_as_uint(As[1][(rb + g) * PA + ko + 4 + t4]);
                al[3] = __float_as_uint(As[1][(rb + 8 + g) * PA + ko + 4 + t4]);
                #pragma unroll
                for (int nt = 0; nt < 4; nt++) {
                    mma_tf32(acc[mt][nt], ah, bh[nt]);
                    mma_tf32(acc[mt][nt], ah, bl[nt]);
                    mma_tf32(acc[mt][nt], al, bh[nt]);
                }
            }
        }
        __syncthreads();
    }
    #pragma unroll
    for (int mt = 0; mt < 2; mt++) {
        int r0 = row0 + wm * 32 + mt * 16 + g;
        #pragma unroll
        for (int nt = 0; nt < 4; nt++) {
            int cc = wn * 32 + nt * 8 + 2 * t4;
            if (r0 < NN)
                *(__half2*)(C16 + (size_t)r0 * BN + cc) =
                    __floats2half2_rn(acc[mt][nt][0], acc[mt][nt][1]);
            if (r0 + 8 < NN)
                *(__half2*)(C16 + (size_t)(r0 + 8) * BN + cc) =
                    __floats2half2_rn(acc[mt][nt][2], acc[mt][nt][3]);
        }
    }
    if (FUSE) {
        float asv[4][2], adv[4][2];
        #pragma unroll
        for (int nt = 0; nt < 4; nt++) {
            int c = wn * 32 + nt * 8 + 2 * t4;
            asv[nt][0] = a_s[c]; asv[nt][1] = a_s[c + 1];
            adv[nt][0] = a_d[c]; adv[nt][1] = a_d[c + 1];
        }
        float* gasf = (float*)g_as;
        float* gadf = (float*)g_ad;
        #pragma unroll
        for (int mt = 0; mt < 2; mt++) {
            #pragma unroll
            for (int hf = 0; hf < 2; hf++) {
                int r = row0 + wm * 32 + mt * 16 + hf * 8 + g;
                float pa = 0.f, pd = 0.f;
                #pragma unroll
                for (int nt = 0; nt < 4; nt++) {
                    pa = fmaf(acc[mt][nt][2 * hf], asv[nt][0], pa);
                    pa = fmaf(acc[mt][nt][2 * hf + 1], asv[nt][1], pa);
                    pd = fmaf(acc[mt][nt][2 * hf], adv[nt][0], pd);
                    pd = fmaf(acc[mt][nt][2 * hf + 1], adv[nt][1], pd);
                }
                pa += __shfl_xor_sync(0xffffffffu, pa, 1);
                pa += __shfl_xor_sync(0xffffffffu, pa, 2);
                pd += __shfl_xor_sync(0xffffffffu, pd, 1);
                pd += __shfl_xor_sync(0xffffffffu, pd, 2);
                if (t4 == 0 && r < NN) {
                    gasf[r * 4 + wn] = pa;
                    gadf[r * 4 + wn] = pd;
                }
            }
        }
    }
}

// ---------------- per-node attention coefficients (layer 3, C=40) --------
__global__ void k_alpha40(const __half* __restrict__ h, const float* __restrict__ a_s,
                          const float* __restrict__ a_d) {
    int warp = (blockIdx.x * blockDim.x + threadIdx.x) >> 5;
    if (warp >= NN) return;
    int lane = threadIdx.x & 31;
    float pa[4], pd[4];
    #pragma unroll
    for (int hh = 0; hh < 4; hh++) {
        float hv = __half2float(h[(size_t)warp * 160 + hh * 40 + lane]);
        pa[hh] = hv * a_s[hh * 40 + lane];
        pd[hh] = hv * a_d[hh * 40 + lane];
        if (lane < 8) {
            float hv2 = __half2float(h[(size_t)warp * 160 + hh * 40 + 32 + lane]);
            pa[hh] = fmaf(hv2, a_s[hh * 40 + 32 + lane], pa[hh]);
            pd[hh] = fmaf(hv2, a_d[hh * 40 + 32 + lane], pd[hh]);
        }
    }
    #pragma unroll
    for (int hh = 0; hh < 4; hh++) {
        #pragma unroll
        for (int off = 16; off; off >>= 1) {
            pa[hh] += __shfl_xor_sync(0xffffffffu, pa[hh], off);
            pd[hh] += __shfl_xor_sync(0xffffffffu, pd[hh], off);
        }
    }
    if (lane == 0) {
        g_as[warp] = make_float4(pa[0], pa[1], pa[2], pa[3]);
        g_ad[warp] = make_float4(pd[0], pd[1], pd[2], pd[3]);
    }
}

// ---------------- aggregation, concat layers (128 ch, batched gather) ----
__global__ void k_agg128(const __half* __restrict__ h, const float* __restrict__ bias,
                         const float* __restrict__ resid, float* __restrict__ out) {
    int warp = (blockIdx.x * blockDim.x + threadIdx.x) >> 5;
    if (warp >= NN) return;
    int lane = threadIdx.x & 31;
    int hd = lane >> 3;
    float adv = ((const float*)&g_ad[warp])[hd];
    int beg = g_rowptr[warp], end = g_rowptr[warp + 1];
    const float* gasf = (const float*)g_as;

    float4 acc = make_float4(0.f, 0.f, 0.f, 0.f);
    float ss = 0.f;
    int j = beg;
    // 4-edge batches: independent index/coeff/feature loads -> MLP ~4
    for (; j + 4 <= end; j += 4) {
        int s0 = __ldg(&g_col[j]);
        int s1 = __ldg(&g_col[j + 1]);
        int s2 = __ldg(&g_col[j + 2]);
        int s3 = __ldg(&g_col[j + 3]);
        float e0 = gasf[s0 * 4 + hd];
        float e1 = gasf[s1 * 4 + hd];
        float e2 = gasf[s2 * 4 + hd];
        float e3 = gasf[s3 * 4 + hd];
        uint2 r0 = *(const uint2*)(h + (size_t)s0 * 128 + lane * 4);
        uint2 r1 = *(const uint2*)(h + (size_t)s1 * 128 + lane * 4);
        uint2 r2 = *(const uint2*)(h + (size_t)s2 * 128 + lane * 4);
        uint2 r3 = *(const uint2*)(h + (size_t)s3 * 128 + lane * 4);
        e0 += adv; e0 = e0 > 0.f ? e0 : NEG * e0; float w0 = __expf(e0);
        e1 += adv; e1 = e1 > 0.f ? e1 : NEG * e1; float w1 = __expf(e1);
        e2 += adv; e2 = e2 > 0.f ? e2 : NEG * e2; float w2 = __expf(e2);
        e3 += adv; e3 = e3 > 0.f ? e3 : NEG * e3; float w3 = __expf(e3);
        ss += (w0 + w1) + (w2 + w3);
        float2 a0 = __half22float2(*(__half2*)&r0.x), b0 = __half22float2(*(__half2*)&r0.y);
        float2 a1 = __half22float2(*(__half2*)&r1.x), b1 = __half22float2(*(__half2*)&r1.y);
        float2 a2 = __half22float2(*(__half2*)&r2.x), b2 = __half22float2(*(__half2*)&r2.y);
        float2 a3 = __half22float2(*(__half2*)&r3.x), b3 = __half22float2(*(__half2*)&r3.y);
        acc.x = fmaf(w0, a0.x, fmaf(w1, a1.x, fmaf(w2, a2.x, fmaf(w3, a3.x, acc.x))));
        acc.y = fmaf(w0, a0.y, fmaf(w1, a1.y, fmaf(w2, a2.y, fmaf(w3, a3.y, acc.y))));
        acc.z = fmaf(w0, b0.x, fmaf(w1, b1.x, fmaf(w2, b2.x, fmaf(w3, b3.x, acc.z))));
        acc.w = fmaf(w0, b0.y, fmaf(w1, b1.y, fmaf(w2, b2.y, fmaf(w3, b3.y, acc.w))));
    }
    for (; j < end; j++) {
        int s = __ldg(&g_col[j]);
        float e = gasf[s * 4 + hd] + adv;
        e = e > 0.f ? e : NEG * e;
        float w = __expf(e);
        ss += w;
        uint2 hraw = *(const uint2*)(h + (size_t)s * 128 + lane * 4);
        float2 f0 = __half22float2(*(__half2*)&hraw.x);
        float2 f1 = __half22float2(*(__half2*)&hraw.y);
        acc.x = fmaf(w, f0.x, acc.x);
        acc.y = fmaf(w, f0.y, acc.y);
        acc.z = fmaf(w, f1.x, acc.z);
        acc.w = fmaf(w, f1.y, acc.w);
    }
    float inv = 1.f / ss;
    int ch = lane * 4;
    float4 b = *(const float4*)(bias + ch);
    float4 o = make_float4(acc.x * inv + b.x, acc.y * inv + b.y,
                           acc.z * inv + b.z, acc.w * inv + b.w);
    if (resid) {
        float4 r = *(const float4*)(resid + (size_t)warp * 128 + ch);
        o.x += r.x; o.y += r.y; o.z += r.z; o.w += r.w;
    }
    o.x = o.x > 0.f ? o.x : (__expf(o.x) - 1.f);
    o.y = o.y > 0.f ? o.y : (__expf(o.y) - 1.f);
    o.z = o.z > 0.f ? o.z : (__expf(o.z) - 1.f);
    o.w = o.w > 0.f ? o.w : (__expf(o.w) - 1.f);
    *(float4*)(out + (size_t)warp * 128 + ch) = o;
}

// ---------------- aggregation, final layer (160 -> head-mean 40) ---------
__global__ void k_agg40(const __half* __restrict__ h, const float* __restrict__ b3,
                        float* __restrict__ out) {
    int warp = (blockIdx.x * blockDim.x + threadIdx.x) >> 5;
    if (warp >= NN) return;
    int lane = threadIdx.x & 31;
    int hd = lane >> 3;
    float adv = ((const float*)&g_ad[warp])[hd];
    int beg = g_rowptr[warp], end = g_rowptr[warp + 1];
    const float* gasf = (const float*)g_as;

    float acc[5] = {0.f, 0.f, 0.f, 0.f, 0.f};
    float ss = 0.f;
    int j = beg;
    // 2-edge batches (5 scalar feature loads each; 2x index/coeff MLP)
    for (; j + 2 <= end; j += 2) {
        int s0 = __ldg(&g_col[j]);
        int s1 = __ldg(&g_col[j + 1]);
        float e0 = gasf[s0 * 4 + hd];
        float e1 = gasf[s1 * 4 + hd];
        const __half* hp0 = h + (size_t)s0 * 160 + lane * 5;
        const __half* hp1 = h + (size_t)s1 * 160 + lane * 5;
        float f0[5], f1[5];
        #pragma unroll
        for (int i = 0; i < 5; i++) f0[i] = __half2float(__ldg(hp0 + i));
        #pragma unroll
        for (int i = 0; i < 5; i++) f1[i] = __half2float(__ldg(hp1 + i));
        e0 += adv; e0 = e0 > 0.f ? e0 : NEG * e0; float w0 = __expf(e0);
        e1 += adv; e1 = e1 > 0.f ? e1 : NEG * e1; float w1 = __expf(e1);
        ss += w0 + w1;
        #pragma unroll
        for (int i = 0; i < 5; i++)
            acc[i] = fmaf(w0, f0[i], fmaf(w1, f1[i], acc[i]));
    }
    for (; j < end; j++) {
        int s = __ldg(&g_col[j]);
        float e = gasf[s * 4 + hd] + adv;
        e = e > 0.f ? e : NEG * e;
        float w = __expf(e);
        ss += w;
        const __half* hp = h + (size_t)s * 160 + lane * 5;
        #pragma unroll
        for (int i = 0; i < 5; i++)
            acc[i] = fmaf(w, __half2float(__ldg(hp + i)), acc[i]);
    }
    float inv = 1.f / ss;
    float r[5];
    #pragma unroll
    for (int i = 0; i < 5; i++) {
        float v = acc[i] * inv;
        v += __shfl_xor_sync(0xffffffffu, v, 8);
        v += __shfl_xor_sync(0xffffffffu, v, 16);
        r[i] = v * 0.25f;
    }
    if (lane < 8) {
        int c0 = lane * 5;
        #pragma unroll
        for (int i = 0; i < 5; i++)
            out[(size_t)warp * 40 + c0 + i] = r[i] + b3[c0 + i];
    }
}

// ---------------- launch ---------------------------------------------------
extern "C" void kernel_launch(void* const* d_in, const int* in_sizes, int n_in,
                              void* d_out, int out_size) {
    const float* x   = (const float*)d_in[0];
    const int*   ei  = (const int*)d_in[1];
    const float* W1  = (const float*)d_in[2];
    const float* as1 = (const float*)d_in[3];
    const float* ad1 = (const float*)d_in[4];
    const float* b1  = (const float*)d_in[5];
    const float* W2  = (const float*)d_in[6];
    const float* as2 = (const float*)d_in[7];
    const float* ad2 = (const float*)d_in[8];
    const float* b2  = (const float*)d_in[9];
    const float* W3  = (const float*)d_in[10];
    const float* as3 = (const float*)d_in[11];
    const float* ad3 = (const float*)d_in[12];
    const float* b3  = (const float*)d_in[13];
    float* out = (float*)d_out;

    __half* g_h_p;
    float *g_x1_p, *g_x2_p;
    void *cnt_p, *cur_p;
    cudaGetSymbolAddress((void**)&g_h_p,  g_h16);
    cudaGetSymbolAddress((void**)&g_x1_p, g_x1);
    cudaGetSymbolAddress((void**)&g_x2_p, g_x2);
    cudaGetSymbolAddress(&cnt_p, g_cnt);
    cudaGetSymbolAddress(&cur_p, g_cur);

    const int WB = 256;
    const int nodeBlocks = (NN * 32 + WB - 1) / WB;
    const int edgeBlocks = (ETOT + 255) / 256;
    const int gemmBlocks = (NN + 63) / 64;

    // CSR build (shared by all 3 layers)
    cudaMemsetAsync(cnt_p, 0, NN * sizeof(int));
    cudaMemsetAsync(cur_p, 0, NN * sizeof(int));
    k_hist<<<edgeBlocks, 256>>>(ei);
    k_scan<<<1, 1024>>>();
    k_scatter<<<edgeBlocks, 256>>>(ei);

    // ---- layer 1 ----
    k_tgemm<128, true><<<gemmBlocks, 256>>>(x, W1, g_h_p, as1, ad1);
    k_agg128<<<nodeBlocks, WB>>>(g_h_p, b1, nullptr, g_x1_p);

    // ---- layer 2 ----
    k_tgemm<128, true><<<gemmBlocks, 256>>>(g_x1_p, W2, g_h_p, as2, ad2);
    k_agg128<<<nodeBlocks, WB>>>(g_h_p, b2, g_x1_p, g_x2_p);

    // ---- layer 3 ----
    k_tgemm<160, false><<<gemmBlocks, 320>>>(g_x2_p, W3, g_h_p, nullptr, nullptr);
    k_alpha40<<<nodeBlocks, WB>>>(g_h_p, as3, ad3);
    k_agg40<<<nodeBlocks, WB>>>(g_h_p, b3, out);
}

// round 13
// speedup vs baseline: 1.0697x; 1.0463x over previous
#include <cuda_runtime.h>
#include <cuda_fp16.h>
#include <stdint.h>
#include <math.h>

#define NN 50000
#define EE 800000
#define ETOT 850000
#define NEG 0.2f

// ---------------- scratch (static device globals) -------------------------
__device__ int    g_cnt[NN];
__device__ int    g_cur[NN];
__device__ int    g_rowptr[NN + 1];
__device__ int    g_col[ETOT];
__device__ __half g_h16[(size_t)NN * 160];
__device__ float  g_x1[(size_t)NN * 128];
__device__ float  g_x2[(size_t)NN * 128];
__device__ __align__(16) float4 g_as[NN];
__device__ __align__(16) float4 g_ad[NN];

// ---------------- CSR build ----------------------------------------------
__global__ void k_hist(const int* __restrict__ ei) {
    int e = blockIdx.x * blockDim.x + threadIdx.x;
    if (e >= ETOT) return;
    int d = (e < EE) ? ei[EE + e] : (e - EE);
    atomicAdd(&g_cnt[d], 1);
}

__global__ void k_scan() {
    const int CH = (NN + 1023) / 1024;  // 49
    __shared__ int warp_sums[32];
    int tid = threadIdx.x;
    int lane = tid & 31, wid = tid >> 5;
    int base = tid * CH;
    int local = 0;
    for (int i = 0; i < CH; i++) {
        int idx = base + i;
        if (idx < NN) local += g_cnt[idx];
    }
    int x = local;
    #pragma unroll
    for (int off = 1; off < 32; off <<= 1) {
        int y = __shfl_up_sync(0xffffffffu, x, off);
        if (lane >= off) x += y;
    }
    if (lane == 31) warp_sums[wid] = x;
    __syncthreads();
    if (wid == 0) {
        int w = warp_sums[lane];
        #pragma unroll
        for (int off = 1; off < 32; off <<= 1) {
            int y = __shfl_up_sync(0xffffffffu, w, off);
            if (lane >= off) w += y;
        }
        warp_sums[lane] = w;
    }
    __syncthreads();
    int ex = x - local + ((wid == 0) ? 0 : warp_sums[wid - 1]);
    int running = ex;
    for (int i = 0; i < CH; i++) {
        int idx = base + i;
        if (idx < NN) { g_rowptr[idx] = running; running += g_cnt[idx]; }
    }
    if (tid == 1023) g_rowptr[NN] = running;
}

__global__ void k_scatter(const int* __restrict__ ei) {
    int e = blockIdx.x * blockDim.x + threadIdx.x;
    if (e >= ETOT) return;
    int s, d;
    if (e < EE) { s = ei[e]; d = ei[EE + e]; }
    else        { s = d = e - EE; }
    int pos = g_rowptr[d] + atomicAdd(&g_cur[d], 1);
    g_col[pos] = s;
}

// ---------------- tf32x2 tensor-core GEMM (fp16 output) -------------------
__device__ __forceinline__ uint32_t f2tf32(float x) {
    uint32_t r;
    asm("cvt.rna.tf32.f32 %0, %1;" : "=r"(r) : "f"(x));
    return r;
}

__device__ __forceinline__ void split4(float4 v, float4& h4, float4& l4) {
    h4.x = __uint_as_float(f2tf32(v.x)); l4.x = __uint_as_float(f2tf32(v.x - h4.x));
    h4.y = __uint_as_float(f2tf32(v.y)); l4.y = __uint_as_float(f2tf32(v.y - h4.y));
    h4.z = __uint_as_float(f2tf32(v.z)); l4.z = __uint_as_float(f2tf32(v.z - h4.z));
    h4.w = __uint_as_float(f2tf32(v.w)); l4.w = __uint_as_float(f2tf32(v.w - h4.w));
}

__device__ __forceinline__ void mma_tf32(float* d, const uint32_t* a, const uint32_t* b) {
    asm volatile(
        "mma.sync.aligned.m16n8k8.row.col.f32.tf32.tf32.f32 "
        "{%0,%1,%2,%3}, {%4,%5,%6,%7}, {%8,%9}, {%0,%1,%2,%3};\n"
        : "+f"(d[0]), "+f"(d[1]), "+f"(d[2]), "+f"(d[3])
        : "r"(a[0]), "r"(a[1]), "r"(a[2]), "r"(a[3]), "r"(b[0]), "r"(b[1]));
}

// C16[M,BN] = half(A[M,128] @ B[128,BN]).  64xBN block tile, warp = 32x32.
// Single-buffer smem + register prefetch: next tile's global loads are issued
// before the MMA section so their latency retires under compute.
template<int BN, bool FUSE>
__global__ void __launch_bounds__(64 * (BN / 32), (BN == 128 ? 3 : 2))
k_tgemm(const float* __restrict__ A, const float* __restrict__ B,
        __half* __restrict__ C16,
        const float* __restrict__ a_s, const float* __restrict__ a_d) {
    const int NWN = BN / 32;
    const int NT = 64 * NWN;
    const int PA = 20;        // 20 mod 32 -> conflict-free frag loads
    const int PB = BN + 8;    // (BN+8) mod 32 == 8 -> conflict-free
    __shared__ float As[2][64 * PA];          // [hi/lo]
    __shared__ float Bs[2][16 * (BN + 8)];
    const int tid = threadIdx.x;
    const int w = tid >> 5, lane = tid & 31;
    const int wm = w / NWN, wn = w % NWN;
    const int row0 = blockIdx.x * 64;
    const int g = lane >> 2, t4 = lane & 3;

    float acc[2][4][4];
    #pragma unroll
    for (int mt = 0; mt < 2; mt++)
        #pragma unroll
        for (int nt = 0; nt < 4; nt++)
            #pragma unroll
            for (int i = 0; i < 4; i++) acc[mt][nt][i] = 0.f;

    // per-thread fixed staging coordinates
    const int ar = tid >> 2, ac4 = tid & 3;        // A (tid<256 only)
    const bool aval = (tid < 256) && (row0 + ar < NN);
    const float* aptr = A + (size_t)(row0 + ar) * 128 + ac4 * 4;  // + kkcol
    int br_[2], bc_[2];
    const float* bptr[2];
    #pragma unroll
    for (int i = 0; i < 2; i++) {
        int idx = tid + i * NT;
        br_[i] = idx / (BN / 4);
        bc_[i] = idx % (BN / 4);
        bptr[i] = B + (size_t)br_[i] * BN + bc_[i] * 4;           // + kkcol*BN
    }

    // prologue: prefetch tile 0
    float4 aR = aval ? *(const float4*)(aptr) : make_float4(0.f, 0.f, 0.f, 0.f);
    float4 bR0 = *(const float4*)(bptr[0]);
    float4 bR1 = *(const float4*)(bptr[1]);

    #pragma unroll
    for (int kk = 0; kk < 8; kk++) {
        // stage current regs -> smem (split hi/lo)
        if (tid < 256) {
            float4 h4, l4; split4(aR, h4, l4);
            *(float4*)&As[0][ar * PA + ac4 * 4] = h4;
            *(float4*)&As[1][ar * PA + ac4 * 4] = l4;
        }
        {
            float4 h4, l4;
            split4(bR0, h4, l4);
            *(float4*)&Bs[0][br_[0] * PB + bc_[0] * 4] = h4;
            *(float4*)&Bs[1][br_[0] * PB + bc_[0] * 4] = l4;
            split4(bR1, h4, l4);
            *(float4*)&Bs[0][br_[1] * PB + bc_[1] * 4] = h4;
            *(float4*)&Bs[1][br_[1] * PB + bc_[1] * 4] = l4;
        }
        __syncthreads();
        // issue next tile's global loads (latency hidden under MMA below)
        if (kk < 7) {
            const int kc = (kk + 1) * 16;
            aR = aval ? *(const float4*)(aptr + kc) : make_float4(0.f, 0.f, 0.f, 0.f);
            bR0 = *(const float4*)(bptr[0] + (size_t)kc * BN);
            bR1 = *(const float4*)(bptr[1] + (size_t)kc * BN);
        }
        // compute
        #pragma unroll
        for (int s0 = 0; s0 < 2; s0++) {
            const int ko = s0 * 8;
            uint32_t bh[4][2], bl[4][2];
            #pragma unroll
            for (int nt = 0; nt < 4; nt++) {
                int colb = wn * 32 + nt * 8 + g;
                bh[nt][0] = __float_as_uint(Bs[0][(ko + t4) * PB + colb]);
                bh[nt][1] = __float_as_uint(Bs[0][(ko + 4 + t4) * PB + colb]);
                bl[nt][0] = __float_as_uint(Bs[1][(ko + t4) * PB + colb]);
                bl[nt][1] = __float_as_uint(Bs[1][(ko + 4 + t4) * PB + colb]);
            }
            #pragma unroll
            for (int mt = 0; mt < 2; mt++) {
                const int rb = wm * 32 + mt * 16;
                uint32_t ah[4], al[4];
                ah[0] = __float_as_uint(As[0][(rb + g) * PA + ko + t4]);
                ah[1] = __float_as_uint(As[0][(rb + 8 + g) * PA + ko + t4]);
                ah[2] = __float_as_uint(As[0][(rb + g) * PA + ko + 4 + t4]);
                ah[3] = __float_as_uint(As[0][(rb + 8 + g) * PA + ko + 4 + t4]);
                al[0] = __float_as_uint(As[1][(rb + g) * PA + ko + t4]);
                al[1] = __float_as_uint(As[1][(rb + 8 + g) * PA + ko + t4]);
                al[2] = __float_as_uint(As[1][(rb + g) * PA + ko + 4 + t4]);
                al[3] = __float_as_uint(As[1][(rb + 8 + g) * PA + ko + 4 + t4]);
                #pragma unroll
                for (int nt = 0; nt < 4; nt++) {
                    mma_tf32(acc[mt][nt], ah, bh[nt]);
                    mma_tf32(acc[mt][nt], ah, bl[nt]);
                    mma_tf32(acc[mt][nt], al, bh[nt]);
                }
            }
        }
        if (kk < 7) __syncthreads();   // readers done before next store
    }
    // store C as fp16
    #pragma unroll
    for (int mt = 0; mt < 2; mt++) {
        int r0 = row0 + wm * 32 + mt * 16 + g;
        #pragma unroll
        for (int nt = 0; nt < 4; nt++) {
            int cc = wn * 32 + nt * 8 + 2 * t4;
            if (r0 < NN)
                *(__half2*)(C16 + (size_t)r0 * BN + cc) =
                    __floats2half2_rn(acc[mt][nt][0], acc[mt][nt][1]);
            if (r0 + 8 < NN)
                *(__half2*)(C16 + (size_t)(r0 + 8) * BN + cc) =
                    __floats2half2_rn(acc[mt][nt][2], acc[mt][nt][3]);
        }
    }
    if (FUSE) {
        float asv[4][2], adv[4][2];
        #pragma unroll
        for (int nt = 0; nt < 4; nt++) {
            int c = wn * 32 + nt * 8 + 2 * t4;
            asv[nt][0] = a_s[c]; asv[nt][1] = a_s[c + 1];
            adv[nt][0] = a_d[c]; adv[nt][1] = a_d[c + 1];
        }
        float* gasf = (float*)g_as;
        float* gadf = (float*)g_ad;
        #pragma unroll
        for (int mt = 0; mt < 2; mt++) {
            #pragma unroll
            for (int hf = 0; hf < 2; hf++) {
                int r = row0 + wm * 32 + mt * 16 + hf * 8 + g;
                float pa = 0.f, pd = 0.f;
                #pragma unroll
                for (int nt = 0; nt < 4; nt++) {
                    pa = fmaf(acc[mt][nt][2 * hf], asv[nt][0], pa);
                    pa = fmaf(acc[mt][nt][2 * hf + 1], asv[nt][1], pa);
                    pd = fmaf(acc[mt][nt][2 * hf], adv[nt][0], pd);
                    pd = fmaf(acc[mt][nt][2 * hf + 1], adv[nt][1], pd);
                }
                pa += __shfl_xor_sync(0xffffffffu, pa, 1);
                pa += __shfl_xor_sync(0xffffffffu, pa, 2);
                pd += __shfl_xor_sync(0xffffffffu, pd, 1);
                pd += __shfl_xor_sync(0xffffffffu, pd, 2);
                if (t4 == 0 && r < NN) {
                    gasf[r * 4 + wn] = pa;
                    gadf[r * 4 + wn] = pd;
                }
            }
        }
    }
}

// ---------------- per-node attention coefficients (layer 3, C=40) --------
__global__ void k_alpha40(const __half* __restrict__ h, const float* __restrict__ a_s,
                          const float* __restrict__ a_d) {
    int warp = (blockIdx.x * blockDim.x + threadIdx.x) >> 5;
    if (warp >= NN) return;
    int lane = threadIdx.x & 31;
    float pa[4], pd[4];
    #pragma unroll
    for (int hh = 0; hh < 4; hh++) {
        float hv = __half2float(h[(size_t)warp * 160 + hh * 40 + lane]);
        pa[hh] = hv * a_s[hh * 40 + lane];
        pd[hh] = hv * a_d[hh * 40 + lane];
        if (lane < 8) {
            float hv2 = __half2float(h[(size_t)warp * 160 + hh * 40 + 32 + lane]);
            pa[hh] = fmaf(hv2, a_s[hh * 40 + 32 + lane], pa[hh]);
            pd[hh] = fmaf(hv2, a_d[hh * 40 + 32 + lane], pd[hh]);
        }
    }
    #pragma unroll
    for (int hh = 0; hh < 4; hh++) {
        #pragma unroll
        for (int off = 16; off; off >>= 1) {
            pa[hh] += __shfl_xor_sync(0xffffffffu, pa[hh], off);
            pd[hh] += __shfl_xor_sync(0xffffffffu, pd[hh], off);
        }
    }
    if (lane == 0) {
        g_as[warp] = make_float4(pa[0], pa[1], pa[2], pa[3]);
        g_ad[warp] = make_float4(pd[0], pd[1], pd[2], pd[3]);
    }
}

// ---------------- aggregation, concat layers (128 ch, batched gather) ----
__global__ void k_agg128(const __half* __restrict__ h, const float* __restrict__ bias,
                         const float* __restrict__ resid, float* __restrict__ out) {
    int warp = (blockIdx.x * blockDim.x + threadIdx.x) >> 5;
    if (warp >= NN) return;
    int lane = threadIdx.x & 31;
    int hd = lane >> 3;
    float adv = ((const float*)&g_ad[warp])[hd];
    int beg = g_rowptr[warp], end = g_rowptr[warp + 1];
    const float* gasf = (const float*)g_as;

    float4 acc = make_float4(0.f, 0.f, 0.f, 0.f);
    float ss = 0.f;
    int j = beg;
    for (; j + 4 <= end; j += 4) {
        int s0 = __ldg(&g_col[j]);
        int s1 = __ldg(&g_col[j + 1]);
        int s2 = __ldg(&g_col[j + 2]);
        int s3 = __ldg(&g_col[j + 3]);
        float e0 = gasf[s0 * 4 + hd];
        float e1 = gasf[s1 * 4 + hd];
        float e2 = gasf[s2 * 4 + hd];
        float e3 = gasf[s3 * 4 + hd];
        uint2 r0 = *(const uint2*)(h + (size_t)s0 * 128 + lane * 4);
        uint2 r1 = *(const uint2*)(h + (size_t)s1 * 128 + lane * 4);
        uint2 r2 = *(const uint2*)(h + (size_t)s2 * 128 + lane * 4);
        uint2 r3 = *(const uint2*)(h + (size_t)s3 * 128 + lane * 4);
        e0 += adv; e0 = e0 > 0.f ? e0 : NEG * e0; float w0 = __expf(e0);
        e1 += adv; e1 = e1 > 0.f ? e1 : NEG * e1; float w1 = __expf(e1);
        e2 += adv; e2 = e2 > 0.f ? e2 : NEG * e2; float w2 = __expf(e2);
        e3 += adv; e3 = e3 > 0.f ? e3 : NEG * e3; float w3 = __expf(e3);
        ss += (w0 + w1) + (w2 + w3);
        float2 a0 = __half22float2(*(__half2*)&r0.x), b0 = __half22float2(*(__half2*)&r0.y);
        float2 a1 = __half22float2(*(__half2*)&r1.x), b1 = __half22float2(*(__half2*)&r1.y);
        float2 a2 = __half22float2(*(__half2*)&r2.x), b2 = __half22float2(*(__half2*)&r2.y);
        float2 a3 = __half22float2(*(__half2*)&r3.x), b3 = __half22float2(*(__half2*)&r3.y);
        acc.x = fmaf(w0, a0.x, fmaf(w1, a1.x, fmaf(w2, a2.x, fmaf(w3, a3.x, acc.x))));
        acc.y = fmaf(w0, a0.y, fmaf(w1, a1.y, fmaf(w2, a2.y, fmaf(w3, a3.y, acc.y))));
        acc.z = fmaf(w0, b0.x, fmaf(w1, b1.x, fmaf(w2, b2.x, fmaf(w3, b3.x, acc.z))));
        acc.w = fmaf(w0, b0.y, fmaf(w1, b1.y, fmaf(w2, b2.y, fmaf(w3, b3.y, acc.w))));
    }
    for (; j < end; j++) {
        int s = __ldg(&g_col[j]);
        float e = gasf[s * 4 + hd] + adv;
        e = e > 0.f ? e : NEG * e;
        float w = __expf(e);
        ss += w;
        uint2 hraw = *(const uint2*)(h + (size_t)s * 128 + lane * 4);
        float2 f0 = __half22float2(*(__half2*)&hraw.x);
        float2 f1 = __half22float2(*(__half2*)&hraw.y);
        acc.x = fmaf(w, f0.x, acc.x);
        acc.y = fmaf(w, f0.y, acc.y);
        acc.z = fmaf(w, f1.x, acc.z);
        acc.w = fmaf(w, f1.y, acc.w);
    }
    float inv = 1.f / ss;
    int ch = lane * 4;
    float4 b = *(const float4*)(bias + ch);
    float4 o = make_float4(acc.x * inv + b.x, acc.y * inv + b.y,
                           acc.z * inv + b.z, acc.w * inv + b.w);
    if (resid) {
        float4 r = *(const float4*)(resid + (size_t)warp * 128 + ch);
        o.x += r.x; o.y += r.y; o.z += r.z; o.w += r.w;
    }
    o.x = o.x > 0.f ? o.x : (__expf(o.x) - 1.f);
    o.y = o.y > 0.f ? o.y : (__expf(o.y) - 1.f);
    o.z = o.z > 0.f ? o.z : (__expf(o.z) - 1.f);
    o.w = o.w > 0.f ? o.w : (__expf(o.w) - 1.f);
    *(float4*)(out + (size_t)warp * 128 + ch) = o;
}

// ---------------- aggregation, final layer (160 -> head-mean 40) ---------
__global__ void k_agg40(const __half* __restrict__ h, const float* __restrict__ b3,
                        float* __restrict__ out) {
    int warp = (blockIdx.x * blockDim.x + threadIdx.x) >> 5;
    if (warp >= NN) return;
    int lane = threadIdx.x & 31;
    int hd = lane >> 3;
    float adv = ((const float*)&g_ad[warp])[hd];
    int beg = g_rowptr[warp], end = g_rowptr[warp + 1];
    const float* gasf = (const float*)g_as;

    float acc[5] = {0.f, 0.f, 0.f, 0.f, 0.f};
    float ss = 0.f;
    int j = beg;
    for (; j + 2 <= end; j += 2) {
        int s0 = __ldg(&g_col[j]);
        int s1 = __ldg(&g_col[j + 1]);
        float e0 = gasf[s0 * 4 + hd];
        float e1 = gasf[s1 * 4 + hd];
        const __half* hp0 = h + (size_t)s0 * 160 + lane * 5;
        const __half* hp1 = h + (size_t)s1 * 160 + lane * 5;
        float f0[5], f1[5];
        #pragma unroll
        for (int i = 0; i < 5; i++) f0[i] = __half2float(__ldg(hp0 + i));
        #pragma unroll
        for (int i = 0; i < 5; i++) f1[i] = __half2float(__ldg(hp1 + i));
        e0 += adv; e0 = e0 > 0.f ? e0 : NEG * e0; float w0 = __expf(e0);
        e1 += adv; e1 = e1 > 0.f ? e1 : NEG * e1; float w1 = __expf(e1);
        ss += w0 + w1;
        #pragma unroll
        for (int i = 0; i < 5; i++)
            acc[i] = fmaf(w0, f0[i], fmaf(w1, f1[i], acc[i]));
    }
    for (; j < end; j++) {
        int s = __ldg(&g_col[j]);
        float e = gasf[s * 4 + hd] + adv;
        e = e > 0.f ? e : NEG * e;
        float w = __expf(e);
        ss += w;
        const __half* hp = h + (size_t)s * 160 + lane * 5;
        #pragma unroll
        for (int i = 0; i < 5; i++)
            acc[i] = fmaf(w, __half2float(__ldg(hp + i)), acc[i]);
    }
    float inv = 1.f / ss;
    float r[5];
    #pragma unroll
    for (int i = 0; i < 5; i++) {
        float v = acc[i] * inv;
        v += __shfl_xor_sync(0xffffffffu, v, 8);
        v += __shfl_xor_sync(0xffffffffu, v, 16);
        r[i] = v * 0.25f;
    }
    if (lane < 8) {
        int c0 = lane * 5;
        #pragma unroll
        for (int i = 0; i < 5; i++)
            out[(size_t)warp * 40 + c0 + i] = r[i] + b3[c0 + i];
    }
}

// ---------------- launch ---------------------------------------------------
extern "C" void kernel_launch(void* const* d_in, const int* in_sizes, int n_in,
                              void* d_out, int out_size) {
    const float* x   = (const float*)d_in[0];
    const int*   ei  = (const int*)d_in[1];
    const float* W1  = (const float*)d_in[2];
    const float* as1 = (const float*)d_in[3];
    const float* ad1 = (const float*)d_in[4];
    const float* b1  = (const float*)d_in[5];
    const float* W2  = (const float*)d_in[6];
    const float* as2 = (const float*)d_in[7];
    const float* ad2 = (const float*)d_in[8];
    const float* b2  = (const float*)d_in[9];
    const float* W3  = (const float*)d_in[10];
    const float* as3 = (const float*)d_in[11];
    const float* ad3 = (const float*)d_in[12];
    const float* b3  = (const float*)d_in[13];
    float* out = (float*)d_out;

    __half* g_h_p;
    float *g_x1_p, *g_x2_p;
    void *cnt_p, *cur_p;
    cudaGetSymbolAddress((void**)&g_h_p,  g_h16);
    cudaGetSymbolAddress((void**)&g_x1_p, g_x1);
    cudaGetSymbolAddress((void**)&g_x2_p, g_x2);
    cudaGetSymbolAddress(&cnt_p, g_cnt);
    cudaGetSymbolAddress(&cur_p, g_cur);

    const int WB = 256;
    const int nodeBlocks = (NN * 32 + WB - 1) / WB;
    const int edgeBlocks = (ETOT + 255) / 256;
    const int gemmBlocks = (NN + 63) / 64;

    // CSR build (shared by all 3 layers)
    cudaMemsetAsync(cnt_p, 0, NN * sizeof(int));
    cudaMemsetAsync(cur_p, 0, NN * sizeof(int));
    k_hist<<<edgeBlocks, 256>>>(ei);
    k_scan<<<1, 1024>>>();
    k_scatter<<<edgeBlocks, 256>>>(ei);

    // ---- layer 1 ----
    k_tgemm<128, true><<<gemmBlocks, 256>>>(x, W1, g_h_p, as1, ad1);
    k_agg128<<<nodeBlocks, WB>>>(g_h_p, b1, nullptr, g_x1_p);

    // ---- layer 2 ----
    k_tgemm<128, true><<<gemmBlocks, 256>>>(g_x1_p, W2, g_h_p, as2, ad2);
    k_agg128<<<nodeBlocks, WB>>>(g_h_p, b2, g_x1_p, g_x2_p);

    // ---- layer 3 ----
    k_tgemm<160, false><<<gemmBlocks, 320>>>(g_x2_p, W3, g_h_p, nullptr, nullptr);
    k_alpha40<<<nodeBlocks, WB>>>(g_h_p, as3, ad3);
    k_agg40<<<nodeBlocks, WB>>>(g_h_p, b3, out);
}

// round 15
// speedup vs baseline: 1.1845x; 1.1073x over previous
#include <cuda_runtime.h>
#include <cuda_fp16.h>
#include <stdint.h>
#include <math.h>

#define NN 50000
#define EE 800000
#define ETOT 850000
#define NEG 0.2f

// ---------------- scratch (static device globals) -------------------------
__device__ int    g_cnt[NN];
__device__ int    g_cur[NN];
__device__ int    g_rowptr[NN + 1];
__device__ int    g_col[ETOT];
__device__ __half g_h16[(size_t)NN * 160];
__device__ float  g_x1[(size_t)NN * 128];
__device__ float  g_x2[(size_t)NN * 128];
__device__ __align__(16) float4 g_as[NN];
__device__ __align__(16) float4 g_ad[NN];

// ---------------- CSR build ----------------------------------------------
__global__ void k_hist(const int* __restrict__ ei) {
    int e = blockIdx.x * blockDim.x + threadIdx.x;
    if (e >= ETOT) return;
    int d = (e < EE) ? ei[EE + e] : (e - EE);
    atomicAdd(&g_cnt[d], 1);
}

__global__ void k_scan() {
    const int CH = (NN + 1023) / 1024;  // 49
    __shared__ int warp_sums[32];
    int tid = threadIdx.x;
    int lane = tid & 31, wid = tid >> 5;
    int base = tid * CH;
    int local = 0;
    for (int i = 0; i < CH; i++) {
        int idx = base + i;
        if (idx < NN) local += g_cnt[idx];
    }
    int x = local;
    #pragma unroll
    for (int off = 1; off < 32; off <<= 1) {
        int y = __shfl_up_sync(0xffffffffu, x, off);
        if (lane >= off) x += y;
    }
    if (lane == 31) warp_sums[wid] = x;
    __syncthreads();
    if (wid == 0) {
        int w = warp_sums[lane];
        #pragma unroll
        for (int off = 1; off < 32; off <<= 1) {
            int y = __shfl_up_sync(0xffffffffu, w, off);
            if (lane >= off) w += y;
        }
        warp_sums[lane] = w;
    }
    __syncthreads();
    int ex = x - local + ((wid == 0) ? 0 : warp_sums[wid - 1]);
    int running = ex;
    for (int i = 0; i < CH; i++) {
        int idx = base + i;
        if (idx < NN) { g_rowptr[idx] = running; running += g_cnt[idx]; }
    }
    if (tid == 1023) g_rowptr[NN] = running;
}

__global__ void k_scatter(const int* __restrict__ ei) {
    int e = blockIdx.x * blockDim.x + threadIdx.x;
    if (e >= ETOT) return;
    int s, d;
    if (e < EE) { s = ei[e]; d = ei[EE + e]; }
    else        { s = d = e - EE; }
    int pos = g_rowptr[d] + atomicAdd(&g_cur[d], 1);
    g_col[pos] = s;
}

// ---------------- tf32 tensor-core GEMM (B split hi/lo, fp16 output) ------
__device__ __forceinline__ uint32_t f2tf32(float x) {
    uint32_t r;
    asm("cvt.rna.tf32.f32 %0, %1;" : "=r"(r) : "f"(x));
    return r;
}

__device__ __forceinline__ float4 tf32_4(float4 v) {
    return make_float4(__uint_as_float(f2tf32(v.x)), __uint_as_float(f2tf32(v.y)),
                       __uint_as_float(f2tf32(v.z)), __uint_as_float(f2tf32(v.w)));
}

__device__ __forceinline__ void split4(float4 v, float4& h4, float4& l4) {
    h4.x = __uint_as_float(f2tf32(v.x)); l4.x = __uint_as_float(f2tf32(v.x - h4.x));
    h4.y = __uint_as_float(f2tf32(v.y)); l4.y = __uint_as_float(f2tf32(v.y - h4.y));
    h4.z = __uint_as_float(f2tf32(v.z)); l4.z = __uint_as_float(f2tf32(v.z - h4.z));
    h4.w = __uint_as_float(f2tf32(v.w)); l4.w = __uint_as_float(f2tf32(v.w - h4.w));
}

__device__ __forceinline__ void mma_tf32(float* d, const uint32_t* a, const uint32_t* b) {
    asm volatile(
        "mma.sync.aligned.m16n8k8.row.col.f32.tf32.tf32.f32 "
        "{%0,%1,%2,%3}, {%4,%5,%6,%7}, {%8,%9}, {%0,%1,%2,%3};\n"
        : "+f"(d[0]), "+f"(d[1]), "+f"(d[2]), "+f"(d[3])
        : "r"(a[0]), "r"(a[1]), "r"(a[2]), "r"(a[3]), "r"(b[0]), "r"(b[1]));
}

// C16[M,BN] = half(A[M,128] @ B[128,BN]).  64xBN block tile, warp = 32x32.
// A stored tf32 (single plane); B split hi/lo: D = ah*bh + ah*bl.
// Register prefetch hides global-load latency under the MMA section.
template<int BN, bool FUSE>
__global__ void __launch_bounds__(64 * (BN / 32), (BN == 128 ? 3 : 2))
k_tgemm(const float* __restrict__ A, const float* __restrict__ B,
        __half* __restrict__ C16,
        const float* __restrict__ a_s, const float* __restrict__ a_d) {
    const int NWN = BN / 32;
    const int NT = 64 * NWN;
    const int PA = 20;        // 20 mod 32 -> conflict-free frag loads
    const int PB = BN + 8;    // (BN+8) mod 32 == 8 -> conflict-free
    __shared__ float As[64 * PA];
    __shared__ float Bs[2][16 * (BN + 8)];
    const int tid = threadIdx.x;
    const int w = tid >> 5, lane = tid & 31;
    const int wm = w / NWN, wn = w % NWN;
    const int row0 = blockIdx.x * 64;
    const int g = lane >> 2, t4 = lane & 3;

    float acc[2][4][4];
    #pragma unroll
    for (int mt = 0; mt < 2; mt++)
        #pragma unroll
        for (int nt = 0; nt < 4; nt++)
            #pragma unroll
            for (int i = 0; i < 4; i++) acc[mt][nt][i] = 0.f;

    // per-thread fixed staging coordinates
    const int ar = tid >> 2, ac4 = tid & 3;        // A (tid<256 only)
    const bool aval = (tid < 256) && (row0 + ar < NN);
    const float* aptr = A + (size_t)(row0 + ar) * 128 + ac4 * 4;  // + kkcol
    int br_[2], bc_[2];
    const float* bptr[2];
    #pragma unroll
    for (int i = 0; i < 2; i++) {
        int idx = tid + i * NT;
        br_[i] = idx / (BN / 4);
        bc_[i] = idx % (BN / 4);
        bptr[i] = B + (size_t)br_[i] * BN + bc_[i] * 4;           // + kkcol*BN
    }

    // prologue: prefetch tile 0
    float4 aR = aval ? *(const float4*)(aptr) : make_float4(0.f, 0.f, 0.f, 0.f);
    float4 bR0 = *(const float4*)(bptr[0]);
    float4 bR1 = *(const float4*)(bptr[1]);

    #pragma unroll
    for (int kk = 0; kk < 8; kk++) {
        // stage current regs -> smem
        if (tid < 256)
            *(float4*)&As[ar * PA + ac4 * 4] = tf32_4(aR);
        {
            float4 h4, l4;
            split4(bR0, h4, l4);
            *(float4*)&Bs[0][br_[0] * PB + bc_[0] * 4] = h4;
            *(float4*)&Bs[1][br_[0] * PB + bc_[0] * 4] = l4;
            split4(bR1, h4, l4);
            *(float4*)&Bs[0][br_[1] * PB + bc_[1] * 4] = h4;
            *(float4*)&Bs[1][br_[1] * PB + bc_[1] * 4] = l4;
        }
        __syncthreads();
        // issue next tile's global loads (latency hidden under MMA below)
        if (kk < 7) {
            const int kc = (kk + 1) * 16;
            aR = aval ? *(const float4*)(aptr + kc) : make_float4(0.f, 0.f, 0.f, 0.f);
            bR0 = *(const float4*)(bptr[0] + (size_t)kc * BN);
            bR1 = *(const float4*)(bptr[1] + (size_t)kc * BN);
        }
        // compute
        #pragma unroll
        for (int s0 = 0; s0 < 2; s0++) {
            const int ko = s0 * 8;
            uint32_t bh[4][2], bl[4][2];
            #pragma unroll
            for (int nt = 0; nt < 4; nt++) {
                int colb = wn * 32 + nt * 8 + g;
                bh[nt][0] = __float_as_uint(Bs[0][(ko + t4) * PB + colb]);
                bh[nt][1] = __float_as_uint(Bs[0][(ko + 4 + t4) * PB + colb]);
                bl[nt][0] = __float_as_uint(Bs[1][(ko + t4) * PB + colb]);
                bl[nt][1] = __float_as_uint(Bs[1][(ko + 4 + t4) * PB + colb]);
            }
            #pragma unroll
            for (int mt = 0; mt < 2; mt++) {
                const int rb = wm * 32 + mt * 16;
                uint32_t ah[4];
                ah[0] = __float_as_uint(As[(rb + g) * PA + ko + t4]);
                ah[1] = __float_as_uint(As[(rb + 8 + g) * PA + ko + t4]);
                ah[2] = __float_as_uint(As[(rb + g) * PA + ko + 4 + t4]);
                ah[3] = __float_as_uint(As[(rb + 8 + g) * PA + ko + 4 + t4]);
                #pragma unroll
                for (int nt = 0; nt < 4; nt++) {
                    mma_tf32(acc[mt][nt], ah, bh[nt]);
                    mma_tf32(acc[mt][nt], ah, bl[nt]);
                }
            }
        }
        if (kk < 7) __syncthreads();   // readers done before next store
    }
    // store C as fp16
    #pragma unroll
    for (int mt = 0; mt < 2; mt++) {
        int r0 = row0 + wm * 32 + mt * 16 + g;
        #pragma unroll
        for (int nt = 0; nt < 4; nt++) {
            int cc = wn * 32 + nt * 8 + 2 * t4;
            if (r0 < NN)
                *(__half2*)(C16 + (size_t)r0 * BN + cc) =
                    __floats2half2_rn(acc[mt][nt][0], acc[mt][nt][1]);
            if (r0 + 8 < NN)
                *(__half2*)(C16 + (size_t)(r0 + 8) * BN + cc) =
                    __floats2half2_rn(acc[mt][nt][2], acc[mt][nt][3]);
        }
    }
    if (FUSE) {
        float asv[4][2], adv[4][2];
        #pragma unroll
        for (int nt = 0; nt < 4; nt++) {
            int c = wn * 32 + nt * 8 + 2 * t4;
            asv[nt][0] = a_s[c]; asv[nt][1] = a_s[c + 1];
            adv[nt][0] = a_d[c]; adv[nt][1] = a_d[c + 1];
        }
        float* gasf = (float*)g_as;
        float* gadf = (float*)g_ad;
        #pragma unroll
        for (int mt = 0; mt < 2; mt++) {
            #pragma unroll
            for (int hf = 0; hf < 2; hf++) {
                int r = row0 + wm * 32 + mt * 16 + hf * 8 + g;
                float pa = 0.f, pd = 0.f;
                #pragma unroll
                for (int nt = 0; nt < 4; nt++) {
                    pa = fmaf(acc[mt][nt][2 * hf], asv[nt][0], pa);
                    pa = fmaf(acc[mt][nt][2 * hf + 1], asv[nt][1], pa);
                    pd = fmaf(acc[mt][nt][2 * hf], adv[nt][0], pd);
                    pd = fmaf(acc[mt][nt][2 * hf + 1], adv[nt][1], pd);
                }
                pa += __shfl_xor_sync(0xffffffffu, pa, 1);
                pa += __shfl_xor_sync(0xffffffffu, pa, 2);
                pd += __shfl_xor_sync(0xffffffffu, pd, 1);
                pd += __shfl_xor_sync(0xffffffffu, pd, 2);
                if (t4 == 0 && r < NN) {
                    gasf[r * 4 + wn] = pa;
                    gadf[r * 4 + wn] = pd;
                }
            }
        }
    }
}

// ---------------- per-node attention coefficients (layer 3, C=40) --------
__global__ void k_alpha40(const __half* __restrict__ h, const float* __restrict__ a_s,
                          const float* __restrict__ a_d) {
    int warp = (blockIdx.x * blockDim.x + threadIdx.x) >> 5;
    if (warp >= NN) return;
    int lane = threadIdx.x & 31;
    float pa[4], pd[4];
    #pragma unroll
    for (int hh = 0; hh < 4; hh++) {
        float hv = __half2float(h[(size_t)warp * 160 + hh * 40 + lane]);
        pa[hh] = hv * a_s[hh * 40 + lane];
        pd[hh] = hv * a_d[hh * 40 + lane];
        if (lane < 8) {
            float hv2 = __half2float(h[(size_t)warp * 160 + hh * 40 + 32 + lane]);
            pa[hh] = fmaf(hv2, a_s[hh * 40 + 32 + lane], pa[hh]);
            pd[hh] = fmaf(hv2, a_d[hh * 40 + 32 + lane], pd[hh]);
        }
    }
    #pragma unroll
    for (int hh = 0; hh < 4; hh++) {
        #pragma unroll
        for (int off = 16; off; off >>= 1) {
            pa[hh] += __shfl_xor_sync(0xffffffffu, pa[hh], off);
            pd[hh] += __shfl_xor_sync(0xffffffffu, pd[hh], off);
        }
    }
    if (lane == 0) {
        g_as[warp] = make_float4(pa[0], pa[1], pa[2], pa[3]);
        g_ad[warp] = make_float4(pd[0], pd[1], pd[2], pd[3]);
    }
}

// ---------------- aggregation, concat layers (128 ch, batched gather) ----
__global__ void k_agg128(const __half* __restrict__ h, const float* __restrict__ bias,
                         const float* __restrict__ resid, float* __restrict__ out) {
    int warp = (blockIdx.x * blockDim.x + threadIdx.x) >> 5;
    if (warp >= NN) return;
    int lane = threadIdx.x & 31;
    int hd = lane >> 3;
    float adv = ((const float*)&g_ad[warp])[hd];
    int beg = g_rowptr[warp], end = g_rowptr[warp + 1];
    const float* gasf = (const float*)g_as;

    float4 acc = make_float4(0.f, 0.f, 0.f, 0.f);
    float ss = 0.f;
    int j = beg;
    for (; j + 4 <= end; j += 4) {
        int s0 = __ldg(&g_col[j]);
        int s1 = __ldg(&g_col[j + 1]);
        int s2 = __ldg(&g_col[j + 2]);
        int s3 = __ldg(&g_col[j + 3]);
        float e0 = gasf[s0 * 4 + hd];
        float e1 = gasf[s1 * 4 + hd];
        float e2 = gasf[s2 * 4 + hd];
        float e3 = gasf[s3 * 4 + hd];
        uint2 r0 = *(const uint2*)(h + (size_t)s0 * 128 + lane * 4);
        uint2 r1 = *(const uint2*)(h + (size_t)s1 * 128 + lane * 4);
        uint2 r2 = *(const uint2*)(h + (size_t)s2 * 128 + lane * 4);
        uint2 r3 = *(const uint2*)(h + (size_t)s3 * 128 + lane * 4);
        e0 += adv; e0 = e0 > 0.f ? e0 : NEG * e0; float w0 = __expf(e0);
        e1 += adv; e1 = e1 > 0.f ? e1 : NEG * e1; float w1 = __expf(e1);
        e2 += adv; e2 = e2 > 0.f ? e2 : NEG * e2; float w2 = __expf(e2);
        e3 += adv; e3 = e3 > 0.f ? e3 : NEG * e3; float w3 = __expf(e3);
        ss += (w0 + w1) + (w2 + w3);
        float2 a0 = __half22float2(*(__half2*)&r0.x), b0 = __half22float2(*(__half2*)&r0.y);
        float2 a1 = __half22float2(*(__half2*)&r1.x), b1 = __half22float2(*(__half2*)&r1.y);
        float2 a2 = __half22float2(*(__half2*)&r2.x), b2 = __half22float2(*(__half2*)&r2.y);
        float2 a3 = __half22float2(*(__half2*)&r3.x), b3 = __half22float2(*(__half2*)&r3.y);
        acc.x = fmaf(w0, a0.x, fmaf(w1, a1.x, fmaf(w2, a2.x, fmaf(w3, a3.x, acc.x))));
        acc.y = fmaf(w0, a0.y, fmaf(w1, a1.y, fmaf(w2, a2.y, fmaf(w3, a3.y, acc.y))));
        acc.z = fmaf(w0, b0.x, fmaf(w1, b1.x, fmaf(w2, b2.x, fmaf(w3, b3.x, acc.z))));
        acc.w = fmaf(w0, b0.y, fmaf(w1, b1.y, fmaf(w2, b2.y, fmaf(w3, b3.y, acc.w))));
    }
    for (; j < end; j++) {
        int s = __ldg(&g_col[j]);
        float e = gasf[s * 4 + hd] + adv;
        e = e > 0.f ? e : NEG * e;
        float w = __expf(e);
        ss += w;
        uint2 hraw = *(const uint2*)(h + (size_t)s * 128 + lane * 4);
        float2 f0 = __half22float2(*(__half2*)&hraw.x);
        float2 f1 = __half22float2(*(__half2*)&hraw.y);
        acc.x = fmaf(w, f0.x, acc.x);
        acc.y = fmaf(w, f0.y, acc.y);
        acc.z = fmaf(w, f1.x, acc.z);
        acc.w = fmaf(w, f1.y, acc.w);
    }
    float inv = 1.f / ss;
    int ch = lane * 4;
    float4 b = *(const float4*)(bias + ch);
    float4 o = make_float4(acc.x * inv + b.x, acc.y * inv + b.y,
                           acc.z * inv + b.z, acc.w * inv + b.w);
    if (resid) {
        float4 r = *(const float4*)(resid + (size_t)warp * 128 + ch);
        o.x += r.x; o.y += r.y; o.z += r.z; o.w += r.w;
    }
    o.x = o.x > 0.f ? o.x : (__expf(o.x) - 1.f);
    o.y = o.y > 0.f ? o.y : (__expf(o.y) - 1.f);
    o.z = o.z > 0.f ? o.z : (__expf(o.z) - 1.f);
    o.w = o.w > 0.f ? o.w : (__expf(o.w) - 1.f);
    *(float4*)(out + (size_t)warp * 128 + ch) = o;
}

// ---------------- aggregation, final layer (160 -> head-mean 40) ---------
__global__ void k_agg40(const __half* __restrict__ h, const float* __restrict__ b3,
                        float* __restrict__ out) {
    int warp = (blockIdx.x * blockDim.x + threadIdx.x) >> 5;
    if (warp >= NN) return;
    int lane = threadIdx.x & 31;
    int hd = lane >> 3;
    float adv = ((const float*)&g_ad[warp])[hd];
    int beg = g_rowptr[warp], end = g_rowptr[warp + 1];
    const float* gasf = (const float*)g_as;

    float acc[5] = {0.f, 0.f, 0.f, 0.f, 0.f};
    float ss = 0.f;
    int j = beg;
    for (; j + 2 <= end; j += 2) {
        int s0 = __ldg(&g_col[j]);
        int s1 = __ldg(&g_col[j + 1]);
        float e0 = gasf[s0 * 4 + hd];
        float e1 = gasf[s1 * 4 + hd];
        const __half* hp0 = h + (size_t)s0 * 160 + lane * 5;
        const __half* hp1 = h + (size_t)s1 * 160 + lane * 5;
        float f0[5], f1[5];
        #pragma unroll
        for (int i = 0; i < 5; i++) f0[i] = __half2float(__ldg(hp0 + i));
        #pragma unroll
        for (int i = 0; i < 5; i++) f1[i] = __half2float(__ldg(hp1 + i));
        e0 += adv; e0 = e0 > 0.f ? e0 : NEG * e0; float w0 = __expf(e0);
        e1 += adv; e1 = e1 > 0.f ? e1 : NEG * e1; float w1 = __expf(e1);
        ss += w0 + w1;
        #pragma unroll
        for (int i = 0; i < 5; i++)
            acc[i] = fmaf(w0, f0[i], fmaf(w1, f1[i], acc[i]));
    }
    for (; j < end; j++) {
        int s = __ldg(&g_col[j]);
        float e = gasf[s * 4 + hd] + adv;
        e = e > 0.f ? e : NEG * e;
        float w = __expf(e);
        ss += w;
        const __half* hp = h + (size_t)s * 160 + lane * 5;
        #pragma unroll
        for (int i = 0; i < 5; i++)
            acc[i] = fmaf(w, __half2float(__ldg(hp + i)), acc[i]);
    }
    float inv = 1.f / ss;
    float r[5];
    #pragma unroll
    for (int i = 0; i < 5; i++) {
        float v = acc[i] * inv;
        v += __shfl_xor_sync(0xffffffffu, v, 8);
        v += __shfl_xor_sync(0xffffffffu, v, 16);
        r[i] = v * 0.25f;
    }
    if (lane < 8) {
        int c0 = lane * 5;
        #pragma unroll
        for (int i = 0; i < 5; i++)
            out[(size_t)warp * 40 + c0 + i] = r[i] + b3[c0 + i];
    }
}

// ---------------- launch ---------------------------------------------------
extern "C" void kernel_launch(void* const* d_in, const int* in_sizes, int n_in,
                              void* d_out, int out_size) {
    const float* x   = (const float*)d_in[0];
    const int*   ei  = (const int*)d_in[1];
    const float* W1  = (const float*)d_in[2];
    const float* as1 = (const float*)d_in[3];
    const float* ad1 = (const float*)d_in[4];
    const float* b1  = (const float*)d_in[5];
    const float* W2  = (const float*)d_in[6];
    const float* as2 = (const float*)d_in[7];
    const float* ad2 = (const float*)d_in[8];
    const float* b2  = (const float*)d_in[9];
    const float* W3  = (const float*)d_in[10];
    const float* as3 = (const float*)d_in[11];
    const float* ad3 = (const float*)d_in[12];
    const float* b3  = (const float*)d_in[13];
    float* out = (float*)d_out;

    __half* g_h_p;
    float *g_x1_p, *g_x2_p;
    void *cnt_p, *cur_p;
    cudaGetSymbolAddress((void**)&g_h_p,  g_h16);
    cudaGetSymbolAddress((void**)&g_x1_p, g_x1);
    cudaGetSymbolAddress((void**)&g_x2_p, g_x2);
    cudaGetSymbolAddress(&cnt_p, g_cnt);
    cudaGetSymbolAddress(&cur_p, g_cur);

    const int WB = 256;
    const int nodeBlocks = (NN * 32 + WB - 1) / WB;
    const int edgeBlocks = (ETOT + 255) / 256;
    const int gemmBlocks = (NN + 63) / 64;

    // CSR build (shared by all 3 layers)
    cudaMemsetAsync(cnt_p, 0, NN * sizeof(int));
    cudaMemsetAsync(cur_p, 0, NN * sizeof(int));
    k_hist<<<edgeBlocks, 256>>>(ei);
    k_scan<<<1, 1024>>>();
    k_scatter<<<edgeBlocks, 256>>>(ei);

    // ---- layer 1 ----
    k_tgemm<128, true><<<gemmBlocks, 256>>>(x, W1, g_h_p, as1, ad1);
    k_agg128<<<nodeBlocks, WB>>>(g_h_p, b1, nullptr, g_x1_p);

    // ---- layer 2 ----
    k_tgemm<128, true><<<gemmBlocks, 256>>>(g_x1_p, W2, g_h_p, as2, ad2);
    k_agg128<<<nodeBlocks, WB>>>(g_h_p, b2, g_x1_p, g_x2_p);

    // ---- layer 3 ----
    k_tgemm<160, false><<<gemmBlocks, 320>>>(g_x2_p, W3, g_h_p, nullptr, nullptr);
    k_alpha40<<<nodeBlocks, WB>>>(g_h_p, as3, ad3);
    k_agg40<<<nodeBlocks, WB>>>(g_h_p, b3, out);
}

// round 16
// speedup vs baseline: 1.3139x; 1.1092x over previous
#include <cuda_runtime.h>
#include <cuda_fp16.h>
#include <stdint.h>
#include <math.h>

#define NN 50000
#define EE 800000
#define ETOT 850000
#define NEG 0.2f

// ---------------- scratch (static device globals) -------------------------
__device__ int    g_cnt[NN];
__device__ int    g_cur[NN];
__device__ int    g_rowptr[NN + 1];
__device__ int    g_col[ETOT];
__device__ __half g_h16[(size_t)NN * 160];
__device__ float  g_x1[(size_t)NN * 128];
__device__ float  g_x2[(size_t)NN * 128];
__device__ __align__(16) float4 g_as[NN];
__device__ __align__(16) float4 g_ad[NN];

// ---------------- CSR build ----------------------------------------------
__global__ void k_hist(const int* __restrict__ ei) {
    int e = blockIdx.x * blockDim.x + threadIdx.x;
    if (e >= ETOT) return;
    int d = (e < EE) ? ei[EE + e] : (e - EE);
    atomicAdd(&g_cnt[d], 1);
}

__global__ void k_scan() {
    const int CH = (NN + 1023) / 1024;  // 49
    __shared__ int warp_sums[32];
    int tid = threadIdx.x;
    int lane = tid & 31, wid = tid >> 5;
    int base = tid * CH;
    int local = 0;
    for (int i = 0; i < CH; i++) {
        int idx = base + i;
        if (idx < NN) local += g_cnt[idx];
    }
    int x = local;
    #pragma unroll
    for (int off = 1; off < 32; off <<= 1) {
        int y = __shfl_up_sync(0xffffffffu, x, off);
        if (lane >= off) x += y;
    }
    if (lane == 31) warp_sums[wid] = x;
    __syncthreads();
    if (wid == 0) {
        int w = warp_sums[lane];
        #pragma unroll
        for (int off = 1; off < 32; off <<= 1) {
            int y = __shfl_up_sync(0xffffffffu, w, off);
            if (lane >= off) w += y;
        }
        warp_sums[lane] = w;
    }
    __syncthreads();
    int ex = x - local + ((wid == 0) ? 0 : warp_sums[wid - 1]);
    int running = ex;
    for (int i = 0; i < CH; i++) {
        int idx = base + i;
        if (idx < NN) { g_rowptr[idx] = running; running += g_cnt[idx]; }
    }
    if (tid == 1023) g_rowptr[NN] = running;
}

__global__ void k_scatter(const int* __restrict__ ei) {
    int e = blockIdx.x * blockDim.x + threadIdx.x;
    if (e >= ETOT) return;
    int s, d;
    if (e < EE) { s = ei[e]; d = ei[EE + e]; }
    else        { s = d = e - EE; }
    int pos = g_rowptr[d] + atomicAdd(&g_cur[d], 1);
    g_col[pos] = s;
}

// ---------------- tf32 tensor-core GEMM (fp16 output) ---------------------
__device__ __forceinline__ uint32_t f2tf32(float x) {
    uint32_t r;
    asm("cvt.rna.tf32.f32 %0, %1;" : "=r"(r) : "f"(x));
    return r;
}

__device__ __forceinline__ float4 tf32_4(float4 v) {
    return make_float4(__uint_as_float(f2tf32(v.x)), __uint_as_float(f2tf32(v.y)),
                       __uint_as_float(f2tf32(v.z)), __uint_as_float(f2tf32(v.w)));
}

__device__ __forceinline__ void mma_tf32(float* d, const uint32_t* a, const uint32_t* b) {
    asm volatile(
        "mma.sync.aligned.m16n8k8.row.col.f32.tf32.tf32.f32 "
        "{%0,%1,%2,%3}, {%4,%5,%6,%7}, {%8,%9}, {%0,%1,%2,%3};\n"
        : "+f"(d[0]), "+f"(d[1]), "+f"(d[2]), "+f"(d[3])
        : "r"(a[0]), "r"(a[1]), "r"(a[2]), "r"(a[3]), "r"(b[0]), "r"(b[1]));
}

// C16[M,BN] = half(A[M,128] @ B[128,BN]).  64xBN block tile, warp = 32x32.
// Pure tf32 operands (A and B single-plane).  Register prefetch hides
// global-load latency under the MMA section.
template<int BN, bool FUSE>
__global__ void __launch_bounds__(64 * (BN / 32), (BN == 128 ? 3 : 2))
k_tgemm(const float* __restrict__ A, const float* __restrict__ B,
        __half* __restrict__ C16,
        const float* __restrict__ a_s, const float* __restrict__ a_d) {
    const int NWN = BN / 32;
    const int NT = 64 * NWN;
    const int PA = 20;        // 20 mod 32 -> conflict-free frag loads
    const int PB = BN + 8;    // (BN+8) mod 32 == 8 -> conflict-free
    __shared__ float As[64 * PA];
    __shared__ float Bs[16 * (BN + 8)];
    const int tid = threadIdx.x;
    const int w = tid >> 5, lane = tid & 31;
    const int wm = w / NWN, wn = w % NWN;
    const int row0 = blockIdx.x * 64;
    const int g = lane >> 2, t4 = lane & 3;

    float acc[2][4][4];
    #pragma unroll
    for (int mt = 0; mt < 2; mt++)
        #pragma unroll
        for (int nt = 0; nt < 4; nt++)
            #pragma unroll
            for (int i = 0; i < 4; i++) acc[mt][nt][i] = 0.f;

    // per-thread fixed staging coordinates
    const int ar = tid >> 2, ac4 = tid & 3;        // A (tid<256 only)
    const bool aval = (tid < 256) && (row0 + ar < NN);
    const float* aptr = A + (size_t)(row0 + ar) * 128 + ac4 * 4;  // + kkcol
    int br_[2], bc_[2];
    const float* bptr[2];
    #pragma unroll
    for (int i = 0; i < 2; i++) {
        int idx = tid + i * NT;
        br_[i] = idx / (BN / 4);
        bc_[i] = idx % (BN / 4);
        bptr[i] = B + (size_t)br_[i] * BN + bc_[i] * 4;           // + kkcol*BN
    }

    // prologue: prefetch tile 0
    float4 aR = aval ? *(const float4*)(aptr) : make_float4(0.f, 0.f, 0.f, 0.f);
    float4 bR0 = *(const float4*)(bptr[0]);
    float4 bR1 = *(const float4*)(bptr[1]);

    #pragma unroll
    for (int kk = 0; kk < 8; kk++) {
        // stage current regs -> smem (tf32-rounded)
        if (tid < 256)
            *(float4*)&As[ar * PA + ac4 * 4] = tf32_4(aR);
        *(float4*)&Bs[br_[0] * PB + bc_[0] * 4] = tf32_4(bR0);
        *(float4*)&Bs[br_[1] * PB + bc_[1] * 4] = tf32_4(bR1);
        __syncthreads();
        // issue next tile's global loads (latency hidden under MMA below)
        if (kk < 7) {
            const int kc = (kk + 1) * 16;
            aR = aval ? *(const float4*)(aptr + kc) : make_float4(0.f, 0.f, 0.f, 0.f);
            bR0 = *(const float4*)(bptr[0] + (size_t)kc * BN);
            bR1 = *(const float4*)(bptr[1] + (size_t)kc * BN);
        }
        // compute
        #pragma unroll
        for (int s0 = 0; s0 < 2; s0++) {
            const int ko = s0 * 8;
            uint32_t bh[4][2];
            #pragma unroll
            for (int nt = 0; nt < 4; nt++) {
                int colb = wn * 32 + nt * 8 + g;
                bh[nt][0] = __float_as_uint(Bs[(ko + t4) * PB + colb]);
                bh[nt][1] = __float_as_uint(Bs[(ko + 4 + t4) * PB + colb]);
            }
            #pragma unroll
            for (int mt = 0; mt < 2; mt++) {
                const int rb = wm * 32 + mt * 16;
                uint32_t ah[4];
                ah[0] = __float_as_uint(As[(rb + g) * PA + ko + t4]);
                ah[1] = __float_as_uint(As[(rb + 8 + g) * PA + ko + t4]);
                ah[2] = __float_as_uint(As[(rb + g) * PA + ko + 4 + t4]);
                ah[3] = __float_as_uint(As[(rb + 8 + g) * PA + ko + 4 + t4]);
                #pragma unroll
                for (int nt = 0; nt < 4; nt++)
                    mma_tf32(acc[mt][nt], ah, bh[nt]);
            }
        }
        if (kk < 7) __syncthreads();   // readers done before next store
    }
    // store C as fp16
    #pragma unroll
    for (int mt = 0; mt < 2; mt++) {
        int r0 = row0 + wm * 32 + mt * 16 + g;
        #pragma unroll
        for (int nt = 0; nt < 4; nt++) {
            int cc = wn * 32 + nt * 8 + 2 * t4;
            if (r0 < NN)
                *(__half2*)(C16 + (size_t)r0 * BN + cc) =
                    __floats2half2_rn(acc[mt][nt][0], acc[mt][nt][1]);
            if (r0 + 8 < NN)
                *(__half2*)(C16 + (size_t)(r0 + 8) * BN + cc) =
                    __floats2half2_rn(acc[mt][nt][2], acc[mt][nt][3]);
        }
    }
    if (FUSE) {
        float asv[4][2], adv[4][2];
        #pragma unroll
        for (int nt = 0; nt < 4; nt++) {
            int c = wn * 32 + nt * 8 + 2 * t4;
            asv[nt][0] = a_s[c]; asv[nt][1] = a_s[c + 1];
            adv[nt][0] = a_d[c]; adv[nt][1] = a_d[c + 1];
        }
        float* gasf = (float*)g_as;
        float* gadf = (float*)g_ad;
        #pragma unroll
        for (int mt = 0; mt < 2; mt++) {
            #pragma unroll
            for (int hf = 0; hf < 2; hf++) {
                int r = row0 + wm * 32 + mt * 16 + hf * 8 + g;
                float pa = 0.f, pd = 0.f;
                #pragma unroll
                for (int nt = 0; nt < 4; nt++) {
                    pa = fmaf(acc[mt][nt][2 * hf], asv[nt][0], pa);
                    pa = fmaf(acc[mt][nt][2 * hf + 1], asv[nt][1], pa);
                    pd = fmaf(acc[mt][nt][2 * hf], adv[nt][0], pd);
                    pd = fmaf(acc[mt][nt][2 * hf + 1], adv[nt][1], pd);
                }
                pa += __shfl_xor_sync(0xffffffffu, pa, 1);
                pa += __shfl_xor_sync(0xffffffffu, pa, 2);
                pd += __shfl_xor_sync(0xffffffffu, pd, 1);
                pd += __shfl_xor_sync(0xffffffffu, pd, 2);
                if (t4 == 0 && r < NN) {
                    gasf[r * 4 + wn] = pa;
                    gadf[r * 4 + wn] = pd;
                }
            }
        }
    }
}

// ---------------- per-node attention coefficients (layer 3, C=40) --------
__global__ void k_alpha40(const __half* __restrict__ h, const float* __restrict__ a_s,
                          const float* __restrict__ a_d) {
    int warp = (blockIdx.x * blockDim.x + threadIdx.x) >> 5;
    if (warp >= NN) return;
    int lane = threadIdx.x & 31;
    float pa[4], pd[4];
    #pragma unroll
    for (int hh = 0; hh < 4; hh++) {
        float hv = __half2float(h[(size_t)warp * 160 + hh * 40 + lane]);
        pa[hh] = hv * a_s[hh * 40 + lane];
        pd[hh] = hv * a_d[hh * 40 + lane];
        if (lane < 8) {
            float hv2 = __half2float(h[(size_t)warp * 160 + hh * 40 + 32 + lane]);
            pa[hh] = fmaf(hv2, a_s[hh * 40 + 32 + lane], pa[hh]);
            pd[hh] = fmaf(hv2, a_d[hh * 40 + 32 + lane], pd[hh]);
        }
    }
    #pragma unroll
    for (int hh = 0; hh < 4; hh++) {
        #pragma unroll
        for (int off = 16; off; off >>= 1) {
            pa[hh] += __shfl_xor_sync(0xffffffffu, pa[hh], off);
            pd[hh] += __shfl_xor_sync(0xffffffffu, pd[hh], off);
        }
    }
    if (lane == 0) {
        g_as[warp] = make_float4(pa[0], pa[1], pa[2], pa[3]);
        g_ad[warp] = make_float4(pd[0], pd[1], pd[2], pd[3]);
    }
}

// ---------------- aggregation, concat layers (128 ch, batched gather) ----
__global__ void k_agg128(const __half* __restrict__ h, const float* __restrict__ bias,
                         const float* __restrict__ resid, float* __restrict__ out) {
    int warp = (blockIdx.x * blockDim.x + threadIdx.x) >> 5;
    if (warp >= NN) return;
    int lane = threadIdx.x & 31;
    int hd = lane >> 3;
    float adv = ((const float*)&g_ad[warp])[hd];
    int beg = g_rowptr[warp], end = g_rowptr[warp + 1];
    const float* gasf = (const float*)g_as;

    float4 acc = make_float4(0.f, 0.f, 0.f, 0.f);
    float ss = 0.f;
    int j = beg;
    for (; j + 4 <= end; j += 4) {
        int s0 = __ldg(&g_col[j]);
        int s1 = __ldg(&g_col[j + 1]);
        int s2 = __ldg(&g_col[j + 2]);
        int s3 = __ldg(&g_col[j + 3]);
        float e0 = gasf[s0 * 4 + hd];
        float e1 = gasf[s1 * 4 + hd];
        float e2 = gasf[s2 * 4 + hd];
        float e3 = gasf[s3 * 4 + hd];
        uint2 r0 = *(const uint2*)(h + (size_t)s0 * 128 + lane * 4);
        uint2 r1 = *(const uint2*)(h + (size_t)s1 * 128 + lane * 4);
        uint2 r2 = *(const uint2*)(h + (size_t)s2 * 128 + lane * 4);
        uint2 r3 = *(const uint2*)(h + (size_t)s3 * 128 + lane * 4);
        e0 += adv; e0 = e0 > 0.f ? e0 : NEG * e0; float w0 = __expf(e0);
        e1 += adv; e1 = e1 > 0.f ? e1 : NEG * e1; float w1 = __expf(e1);
        e2 += adv; e2 = e2 > 0.f ? e2 : NEG * e2; float w2 = __expf(e2);
        e3 += adv; e3 = e3 > 0.f ? e3 : NEG * e3; float w3 = __expf(e3);
        ss += (w0 + w1) + (w2 + w3);
        float2 a0 = __half22float2(*(__half2*)&r0.x), b0 = __half22float2(*(__half2*)&r0.y);
        float2 a1 = __half22float2(*(__half2*)&r1.x), b1 = __half22float2(*(__half2*)&r1.y);
        float2 a2 = __half22float2(*(__half2*)&r2.x), b2 = __half22float2(*(__half2*)&r2.y);
        float2 a3 = __half22float2(*(__half2*)&r3.x), b3 = __half22float2(*(__half2*)&r3.y);
        acc.x = fmaf(w0, a0.x, fmaf(w1, a1.x, fmaf(w2, a2.x, fmaf(w3, a3.x, acc.x))));
        acc.y = fmaf(w0, a0.y, fmaf(w1, a1.y, fmaf(w2, a2.y, fmaf(w3, a3.y, acc.y))));
        acc.z = fmaf(w0, b0.x, fmaf(w1, b1.x, fmaf(w2, b2.x, fmaf(w3, b3.x, acc.z))));
        acc.w = fmaf(w0, b0.y, fmaf(w1, b1.y, fmaf(w2, b2.y, fmaf(w3, b3.y, acc.w))));
    }
    for (; j < end; j++) {
        int s = __ldg(&g_col[j]);
        float e = gasf[s * 4 + hd] + adv;
        e = e > 0.f ? e : NEG * e;
        float w = __expf(e);
        ss += w;
        uint2 hraw = *(const uint2*)(h + (size_t)s * 128 + lane * 4);
        float2 f0 = __half22float2(*(__half2*)&hraw.x);
        float2 f1 = __half22float2(*(__half2*)&hraw.y);
        acc.x = fmaf(w, f0.x, acc.x);
        acc.y = fmaf(w, f0.y, acc.y);
        acc.z = fmaf(w, f1.x, acc.z);
        acc.w = fmaf(w, f1.y, acc.w);
    }
    float inv = 1.f / ss;
    int ch = lane * 4;
    float4 b = *(const float4*)(bias + ch);
    float4 o = make_float4(acc.x * inv + b.x, acc.y * inv + b.y,
                           acc.z * inv + b.z, acc.w * inv + b.w);
    if (resid) {
        float4 r = *(const float4*)(resid + (size_t)warp * 128 + ch);
        o.x += r.x; o.y += r.y; o.z += r.z; o.w += r.w;
    }
    o.x = o.x > 0.f ? o.x : (__expf(o.x) - 1.f);
    o.y = o.y > 0.f ? o.y : (__expf(o.y) - 1.f);
    o.z = o.z > 0.f ? o.z : (__expf(o.z) - 1.f);
    o.w = o.w > 0.f ? o.w : (__expf(o.w) - 1.f);
    *(float4*)(out + (size_t)warp * 128 + ch) = o;
}

// ---------------- aggregation, final layer (160 -> head-mean 40) ---------
__global__ void k_agg40(const __half* __restrict__ h, const float* __restrict__ b3,
                        float* __restrict__ out) {
    int warp = (blockIdx.x * blockDim.x + threadIdx.x) >> 5;
    if (warp >= NN) return;
    int lane = threadIdx.x & 31;
    int hd = lane >> 3;
    float adv = ((const float*)&g_ad[warp])[hd];
    int beg = g_rowptr[warp], end = g_rowptr[warp + 1];
    const float* gasf = (const float*)g_as;

    float acc[5] = {0.f, 0.f, 0.f, 0.f, 0.f};
    float ss = 0.f;
    int j = beg;
    for (; j + 2 <= end; j += 2) {
        int s0 = __ldg(&g_col[j]);
        int s1 = __ldg(&g_col[j + 1]);
        float e0 = gasf[s0 * 4 + hd];
        float e1 = gasf[s1 * 4 + hd];
        const __half* hp0 = h + (size_t)s0 * 160 + lane * 5;
        const __half* hp1 = h + (size_t)s1 * 160 + lane * 5;
        float f0[5], f1[5];
        #pragma unroll
        for (int i = 0; i < 5; i++) f0[i] = __half2float(__ldg(hp0 + i));
        #pragma unroll
        for (int i = 0; i < 5; i++) f1[i] = __half2float(__ldg(hp1 + i));
        e0 += adv; e0 = e0 > 0.f ? e0 : NEG * e0; float w0 = __expf(e0);
        e1 += adv; e1 = e1 > 0.f ? e1 : NEG * e1; float w1 = __expf(e1);
        ss += w0 + w1;
        #pragma unroll
        for (int i = 0; i < 5; i++)
            acc[i] = fmaf(w0, f0[i], fmaf(w1, f1[i], acc[i]));
    }
    for (; j < end; j++) {
        int s = __ldg(&g_col[j]);
        float e = gasf[s * 4 + hd] + adv;
        e = e > 0.f ? e : NEG * e;
        float w = __expf(e);
        ss += w;
        const __half* hp = h + (size_t)s * 160 + lane * 5;
        #pragma unroll
        for (int i = 0; i < 5; i++)
            acc[i] = fmaf(w, __half2float(__ldg(hp + i)), acc[i]);
    }
    float inv = 1.f / ss;
    float r[5];
    #pragma unroll
    for (int i = 0; i < 5; i++) {
        float v = acc[i] * inv;
        v += __shfl_xor_sync(0xffffffffu, v, 8);
        v += __shfl_xor_sync(0xffffffffu, v, 16);
        r[i] = v * 0.25f;
    }
    if (lane < 8) {
        int c0 = lane * 5;
        #pragma unroll
        for (int i = 0; i < 5; i++)
            out[(size_t)warp * 40 + c0 + i] = r[i] + b3[c0 + i];
    }
}

// ---------------- launch ---------------------------------------------------
extern "C" void kernel_launch(void* const* d_in, const int* in_sizes, int n_in,
                              void* d_out, int out_size) {
    const float* x   = (const float*)d_in[0];
    const int*   ei  = (const int*)d_in[1];
    const float* W1  = (const float*)d_in[2];
    const float* as1 = (const float*)d_in[3];
    const float* ad1 = (const float*)d_in[4];
    const float* b1  = (const float*)d_in[5];
    const float* W2  = (const float*)d_in[6];
    const float* as2 = (const float*)d_in[7];
    const float* ad2 = (const float*)d_in[8];
    const float* b2  = (const float*)d_in[9];
    const float* W3  = (const float*)d_in[10];
    const float* as3 = (const float*)d_in[11];
    const float* ad3 = (const float*)d_in[12];
    const float* b3  = (const float*)d_in[13];
    float* out = (float*)d_out;

    __half* g_h_p;
    float *g_x1_p, *g_x2_p;
    void *cnt_p, *cur_p;
    cudaGetSymbolAddress((void**)&g_h_p,  g_h16);
    cudaGetSymbolAddress((void**)&g_x1_p, g_x1);
    cudaGetSymbolAddress((void**)&g_x2_p, g_x2);
    cudaGetSymbolAddress(&cnt_p, g_cnt);
    cudaGetSymbolAddress(&cur_p, g_cur);

    const int WB = 256;
    const int nodeBlocks = (NN * 32 + WB - 1) / WB;
    const int edgeBlocks = (ETOT + 255) / 256;
    const int gemmBlocks = (NN + 63) / 64;

    // CSR build (shared by all 3 layers)
    cudaMemsetAsync(cnt_p, 0, NN * sizeof(int));
    cudaMemsetAsync(cur_p, 0, NN * sizeof(int));
    k_hist<<<edgeBlocks, 256>>>(ei);
    k_scan<<<1, 1024>>>();
    k_scatter<<<edgeBlocks, 256>>>(ei);

    // ---- layer 1 ----
    k_tgemm<128, true><<<gemmBlocks, 256>>>(x, W1, g_h_p, as1, ad1);
    k_agg128<<<nodeBlocks, WB>>>(g_h_p, b1, nullptr, g_x1_p);

    // ---- layer 2 ----
    k_tgemm<128, true><<<gemmBlocks, 256>>>(g_x1_p, W2, g_h_p, as2, ad2);
    k_agg128<<<nodeBlocks, WB>>>(g_h_p, b2, g_x1_p, g_x2_p);

    // ---- layer 3 ----
    k_tgemm<160, false><<<gemmBlocks, 320>>>(g_x2_p, W3, g_h_p, nullptr, nullptr);
    k_alpha40<<<nodeBlocks, WB>>>(g_h_p, as3, ad3);
    k_agg40<<<nodeBlocks, WB>>>(g_h_p, b3, out);
}